// round 12
// baseline (speedup 1.0000x reference)
#include <cuda_runtime.h>
#include <cstdint>

#define DHID  1024
#define NHEAD 16
#define HDIM  64
#define BATCH 4
#define ST    512
#define SI    576
#define SKV   1088
#define QSCALE 0.125f
#define LN_EPS 1e-5f

#define SC_STRIDE 1092   // scores row stride (floats), %32==4
#define Q_STRIDE  68     // Q staging stride, %32==4
#define KV_STRIDE 72     // K/V chunk stride, %32==8

// ---------------- scratch (device globals; allocation-free) ----------------
__device__ float g_ln_qt[BATCH * ST * DHID];
__device__ float g_ln_qi[BATCH * SI * DHID];
__device__ float g_ln_kt[BATCH * ST * DHID];
__device__ float g_ln_ki[BATCH * SI * DHID];
__device__ float g_Q_t[BATCH * NHEAD * ST * HDIM];
__device__ float g_Q_i[BATCH * NHEAD * SI * HDIM];
__device__ float g_K  [BATCH * NHEAD * SKV * HDIM];
__device__ float g_V  [BATCH * NHEAD * SKV * HDIM];
__device__ float g_O_t[BATCH * ST * DHID];
__device__ float g_O_i[BATCH * SI * DHID];
__device__ float g_Wc [7 * DHID * DHID];   // pre-rounded tf32 weights

// ---------------- helpers ----------------
__device__ __forceinline__ uint32_t f2tf(float f) {
    uint32_t u; asm("cvt.rna.tf32.f32 %0, %1;" : "=r"(u) : "f"(f)); return u;
}
__device__ __forceinline__ void mma_tf32(float* d, const uint32_t* a, const uint32_t* b) {
    asm volatile("mma.sync.aligned.m16n8k8.row.col.f32.tf32.tf32.f32 "
                 "{%0,%1,%2,%3}, {%4,%5,%6,%7}, {%8,%9}, {%0,%1,%2,%3};"
                 : "+f"(d[0]), "+f"(d[1]), "+f"(d[2]), "+f"(d[3])
                 : "r"(a[0]), "r"(a[1]), "r"(a[2]), "r"(a[3]), "r"(b[0]), "r"(b[1]));
}
__device__ __forceinline__ uint32_t s2u(const void* p) {
    return (uint32_t)__cvta_generic_to_shared(p);
}
__device__ __forceinline__ void cp16(uint32_t dst, const void* src) {
    asm volatile("cp.async.cg.shared.global [%0], [%1], 16;" :: "r"(dst), "l"(src));
}
__device__ __forceinline__ void cp_commit() {
    asm volatile("cp.async.commit_group;");
}
__device__ __forceinline__ void cp_wait0() {
    asm volatile("cp.async.wait_group 0;" ::: "memory");
}
__device__ __forceinline__ void cp_wait1() {
    asm volatile("cp.async.wait_group 1;" ::: "memory");
}
__device__ __forceinline__ void stg_cs(float* p, float v) {
    asm volatile("st.global.cs.f32 [%0], %1;" :: "l"(p), "f"(v));
}

// ---------------- tf32 pre-round for weights (7 jobs, one launch) ----------------
struct CvtJob { const float* in; float* out; };
struct CvtBatch { CvtJob j[7]; };

__global__ __launch_bounds__(256) void cvt_multi(CvtBatch batch)
{
    const CvtJob jb = batch.j[blockIdx.y];
    const int i = blockIdx.x * 256 + threadIdx.x;     // float4 index
    float4 v = reinterpret_cast<const float4*>(jb.in)[i];
    uint4 u = make_uint4(f2tf(v.x), f2tf(v.y), f2tf(v.z), f2tf(v.w));
    reinterpret_cast<uint4*>(jb.out)[i] = u;
}

// ---------------- LayerNorm (4 jobs; output pre-rounded tf32) ----------------
struct LnJob { const float* x; const float* g; const float* b; float* y; int rows; };
struct LnBatch { LnJob j[4]; };

__global__ __launch_bounds__(256) void ln_multi(LnBatch batch)
{
    const LnJob jb = batch.j[blockIdx.y];
    const int row = blockIdx.x;
    if (row >= jb.rows) return;
    const int t = threadIdx.x;
    const float4 xv = reinterpret_cast<const float4*>(jb.x + (long long)row * DHID)[t];

    float s  = xv.x + xv.y + xv.z + xv.w;
    float sq = xv.x * xv.x + xv.y * xv.y + xv.z * xv.z + xv.w * xv.w;

    __shared__ float red_s[8], red_q[8];
    #pragma unroll
    for (int o = 16; o > 0; o >>= 1) {
        s  += __shfl_xor_sync(0xffffffffu, s,  o);
        sq += __shfl_xor_sync(0xffffffffu, sq, o);
    }
    if ((t & 31) == 0) { red_s[t >> 5] = s; red_q[t >> 5] = sq; }
    __syncthreads();
    float ts = red_s[t & 7], tq = red_q[t & 7];
    #pragma unroll
    for (int o = 4; o > 0; o >>= 1) {
        ts += __shfl_xor_sync(0xffffffffu, ts, o);
        tq += __shfl_xor_sync(0xffffffffu, tq, o);
    }
    ts = __shfl_sync(0xffffffffu, ts, 0);
    tq = __shfl_sync(0xffffffffu, tq, 0);

    const float mean = ts * (1.0f / DHID);
    const float rstd = rsqrtf(tq * (1.0f / DHID) - mean * mean + LN_EPS);

    const float4 gv = reinterpret_cast<const float4*>(jb.g)[t];
    const float4 bv = reinterpret_cast<const float4*>(jb.b)[t];
    uint4 o;
    o.x = f2tf((xv.x - mean) * rstd * gv.x + bv.x);
    o.y = f2tf((xv.y - mean) * rstd * gv.y + bv.y);
    o.z = f2tf((xv.z - mean) * rstd * gv.z + bv.z);
    o.w = f2tf((xv.w - mean) * rstd * gv.w + bv.w);
    reinterpret_cast<uint4*>(jb.y + (long long)row * DHID)[t] = o;
}

// ---------------- batched tf32 GEMM (3-stage cp.async; no inner cvt) ----------------
#define MODE_PLAIN  0   // fp32 store (final outputs)
#define MODE_QSPLIT 1   // tf32-rounded store
#define MODE_KV     2   // tf32-rounded store

struct GemmJob {
    const float* A; const float* Bt; float* C; const float* bias;
    int M; int mode; int S; int off; float alpha;
};
struct GemmBatch { GemmJob j[6]; };

#define GSTG (128 * 36)
#define GEMM_SMEM (6 * GSTG * 4)   // 3 stages x (A+B) = 110592 bytes

__global__ __launch_bounds__(256, 2) void gemm_tf32_multi(GemmBatch batch)
{
    extern __shared__ float smem[];
    const GemmJob jb = batch.j[blockIdx.z];
    const int bm = blockIdx.y * 128;
    if (bm >= jb.M) return;
    const int bn = blockIdx.x * 128;

    const int tid  = threadIdx.x;
    const int w    = tid >> 5;
    const int lane = tid & 31;
    const int gid  = lane >> 2;
    const int ctid = lane & 3;
    const int wm = (w & 1) * 64;
    const int wn = (w >> 1) * 32;
    const int lr = tid >> 3;
    const int lc = (tid & 7) * 4;

    const float* A  = jb.A;
    const float* Bt = jb.Bt;

    auto issue = [&](int k0, int s) {
        float* as = smem + s * 2 * GSTG;
        float* bs = as + GSTG;
        #pragma unroll
        for (int p = 0; p < 4; p++) {
            cp16(s2u(&as[(lr + p * 32) * 36 + lc]), &A [(long long)(bm + lr + p * 32) * DHID + k0 + lc]);
            cp16(s2u(&bs[(lr + p * 32) * 36 + lc]), &Bt[(long long)(bn + lr + p * 32) * DHID + k0 + lc]);
        }
        cp_commit();
    };

    float acc[4][4][4];
    #pragma unroll
    for (int i = 0; i < 4; i++)
        #pragma unroll
        for (int j = 0; j < 4; j++)
            #pragma unroll
            for (int e = 0; e < 4; e++) acc[i][j][e] = 0.0f;

    issue(0, 0);
    issue(32, 1);

    for (int it = 0; it < 32; it++) {
        if (it == 31) cp_wait0(); else cp_wait1();   // tail-aware drain
        __syncthreads();
        if (it + 2 < 32) issue((it + 2) * 32, (it + 2) % 3);

        const uint32_t* as = reinterpret_cast<const uint32_t*>(smem + (it % 3) * 2 * GSTG);
        const uint32_t* bs = as + GSTG;

        #pragma unroll
        for (int ks = 0; ks < 4; ks++) {
            const int kk = ks * 8;
            uint32_t af[4][4], bf[4][2];
            #pragma unroll
            for (int mf = 0; mf < 4; mf++) {
                const int r = wm + mf * 16 + gid;
                af[mf][0] = as[r       * 36 + kk + ctid];
                af[mf][1] = as[(r + 8) * 36 + kk + ctid];
                af[mf][2] = as[r       * 36 + kk + ctid + 4];
                af[mf][3] = as[(r + 8) * 36 + kk + ctid + 4];
            }
            #pragma unroll
            for (int nf = 0; nf < 4; nf++) {
                const int c = wn + nf * 8 + gid;
                bf[nf][0] = bs[c * 36 + kk + ctid];
                bf[nf][1] = bs[c * 36 + kk + ctid + 4];
            }
            #pragma unroll
            for (int mf = 0; mf < 4; mf++)
                #pragma unroll
                for (int nf = 0; nf < 4; nf++)
                    mma_tf32(acc[mf][nf], af[mf], bf[nf]);
        }
    }

    const bool rnd = (jb.mode != MODE_PLAIN);   // Q/K/V consumed as tf32 downstream
    #pragma unroll
    for (int mf = 0; mf < 4; mf++) {
        #pragma unroll
        for (int nf = 0; nf < 4; nf++) {
            const int r0 = bm + wm + mf * 16 + gid;
            const int c0 = bn + wn + nf * 8 + 2 * ctid;
            const float b0 = jb.bias ? jb.bias[c0]     : 0.0f;
            const float b1 = jb.bias ? jb.bias[c0 + 1] : 0.0f;
            float v00 = (acc[mf][nf][0] + b0) * jb.alpha;
            float v01 = (acc[mf][nf][1] + b1) * jb.alpha;
            float v10 = (acc[mf][nf][2] + b0) * jb.alpha;
            float v11 = (acc[mf][nf][3] + b1) * jb.alpha;
            if (rnd) {
                v00 = __uint_as_float(f2tf(v00)); v01 = __uint_as_float(f2tf(v01));
                v10 = __uint_as_float(f2tf(v10)); v11 = __uint_as_float(f2tf(v11));
            }
            long long i0, i1;
            if (jb.mode == MODE_PLAIN) {
                i0 = (long long)r0 * DHID + c0;
                i1 = (long long)(r0 + 8) * DHID + c0;
            } else {
                const int h  = c0 >> 6, hd = c0 & 63;
                const int b_  = r0 / jb.S, s0 = r0 - b_ * jb.S;
                const int b_2 = (r0 + 8) / jb.S, s1 = (r0 + 8) - b_2 * jb.S;
                if (jb.mode == MODE_QSPLIT) {
                    i0 = (((long long)(b_  * NHEAD + h)) * jb.S + s0) * HDIM + hd;
                    i1 = (((long long)(b_2 * NHEAD + h)) * jb.S + s1) * HDIM + hd;
                } else {
                    i0 = (((long long)(b_  * NHEAD + h)) * SKV + jb.off + s0) * HDIM + hd;
                    i1 = (((long long)(b_2 * NHEAD + h)) * SKV + jb.off + s1) * HDIM + hd;
                }
            }
            *reinterpret_cast<float2*>(&jb.C[i0]) = make_float2(v00, v01);
            *reinterpret_cast<float2*>(&jb.C[i1]) = make_float2(v10, v11);
        }
    }
}

// ---------------- fused attention (256 threads, 16 q-rows, 64-row chunks) ----------------
// smem = 111.1 KB -> 2 CTAs/SM. SKV = 17 * 64 exactly (no tail predicates).
#define QROWS 16
#define CHUNK 64
#define NCH (SKV / CHUNK)   // 17
#define ATTN_SMEM ((QROWS * SC_STRIDE + QROWS * Q_STRIDE + 2 * CHUNK * KV_STRIDE) * 4)

__global__ __launch_bounds__(256, 2) void attn_kernel(
    const float* __restrict__ Qt, const float* __restrict__ Qi,
    const float* __restrict__ Kg, const float* __restrict__ Vg,
    float* __restrict__ Wt, float* __restrict__ Wi,
    float* __restrict__ Ot, float* __restrict__ Oi)
{
    extern __shared__ char sm[];
    float* Sc = reinterpret_cast<float*>(sm);           // QROWS x SC_STRIDE
    float* Qs = Sc + QROWS * SC_STRIDE;                 // QROWS x Q_STRIDE
    float* KV = Qs + QROWS * Q_STRIDE;                  // 2 x CHUNK x KV_STRIDE

    const bool isT = blockIdx.x < (ST / QROWS);
    const int  Sq  = isT ? ST : SI;
    const float* Q   = isT ? Qt : Qi;
    float* Wout      = isT ? Wt : Wi;
    float* O         = isT ? Ot : Oi;
    const int qbase  = (isT ? blockIdx.x : blockIdx.x - ST / QROWS) * QROWS;

    const int z = blockIdx.y;
    const int b = z >> 4, h = z & 15;
    const int tid  = threadIdx.x;
    const int w    = tid >> 5;          // 0..7
    const int lane = tid & 31;
    const int gid  = lane >> 2;
    const int ctid = lane & 3;

    auto issueK = [&](int c, int s) {
        float* dst = KV + s * CHUNK * KV_STRIDE;
        #pragma unroll
        for (int i = tid; i < CHUNK * 16; i += 256) {
            const int r = i >> 4, c4 = (i & 15) * 4;
            cp16(s2u(&dst[r * KV_STRIDE + c4]), &Kg[((long long)z * SKV + c * CHUNK + r) * HDIM + c4]);
        }
        cp_commit();
    };
    auto issueV = [&](int c, int s) {
        float* dst = KV + s * CHUNK * KV_STRIDE;
        #pragma unroll
        for (int i = tid; i < CHUNK * 16; i += 256) {
            const int r = i >> 4, c4 = (i & 15) * 4;
            cp16(s2u(&dst[r * KV_STRIDE + c4]), &Vg[((long long)z * SKV + c * CHUNK + r) * HDIM + c4]);
        }
        cp_commit();
    };

    // group 0: Q + K chunk 0
    {
        const int r = tid >> 4, c4 = (tid & 15) * 4;   // 256 = 16 rows x 16 float4
        cp16(s2u(&Qs[r * Q_STRIDE + c4]), &Q[((long long)z * Sq + qbase + r) * HDIM + c4]);
    }
    issueK(0, 0);
    cp_wait0();
    __syncthreads();

    // hoist Q fragments (one m16 tile; pre-rounded tf32 -> raw loads)
    const uint32_t* Qsu = reinterpret_cast<const uint32_t*>(Qs);
    uint32_t qf[8][4];
    #pragma unroll
    for (int ks = 0; ks < 8; ks++) {
        const int kk = ks * 8;
        qf[ks][0] = Qsu[gid       * Q_STRIDE + kk + ctid];
        qf[ks][1] = Qsu[(gid + 8) * Q_STRIDE + kk + ctid];
        qf[ks][2] = Qsu[gid       * Q_STRIDE + kk + ctid + 4];
        qf[ks][3] = Qsu[(gid + 8) * Q_STRIDE + kk + ctid + 4];
    }

    // ---- phase 1: scores (each warp: m16 x n8 strip of the 64-col chunk) ----
    for (int c = 0; c < NCH; c++) {
        if (c > 0) { cp_wait0(); __syncthreads(); }
        if (c + 1 < NCH) issueK(c + 1, (c + 1) & 1);

        const uint32_t* buf = reinterpret_cast<const uint32_t*>(KV + (c & 1) * CHUNK * KV_STRIDE);
        float acc[4] = {0.0f, 0.0f, 0.0f, 0.0f};
        const int col = w * 8 + gid;
        #pragma unroll
        for (int ks = 0; ks < 8; ks++) {
            const int kk = ks * 8;
            uint32_t bf[2];
            bf[0] = buf[col * KV_STRIDE + kk + ctid];
            bf[1] = buf[col * KV_STRIDE + kk + ctid + 4];
            mma_tf32(acc, qf[ks], bf);
        }
        const int c0 = c * CHUNK + w * 8 + 2 * ctid;
        *reinterpret_cast<float2*>(&Sc[gid       * SC_STRIDE + c0]) = make_float2(acc[0], acc[1]);
        *reinterpret_cast<float2*>(&Sc[(gid + 8) * SC_STRIDE + c0]) = make_float2(acc[2], acc[3]);
    }
    __syncthreads();   // all scores in smem; KV buffers free

    // V chunk 0 overlaps the softmax
    issueV(0, 0);

    // ---- phase 2: softmax + streaming w write + in-place tf32 convert ----
    {
        const int r = tid >> 4, l = tid & 15;   // 16 threads per row
        float mx = -1e30f;
        for (int i = l; i < SKV; i += 16) mx = fmaxf(mx, Sc[r * SC_STRIDE + i]);
        #pragma unroll
        for (int o = 8; o > 0; o >>= 1) mx = fmaxf(mx, __shfl_xor_sync(0xffffffffu, mx, o));
        float sum = 0.0f;
        for (int i = l; i < SKV; i += 16) {
            float e = __expf(Sc[r * SC_STRIDE + i] - mx);
            Sc[r * SC_STRIDE + i] = e;
            sum += e;
        }
        #pragma unroll
        for (int o = 8; o > 0; o >>= 1) sum += __shfl_xor_sync(0xffffffffu, sum, o);
        const float inv = 1.0f / sum;
        float* wrow = Wout + ((long long)z * Sq + qbase + r) * SKV;
        uint32_t* Scu = reinterpret_cast<uint32_t*>(Sc);
        for (int i = l; i < SKV; i += 16) {
            const float v = Sc[r * SC_STRIDE + i] * inv;
            stg_cs(&wrow[i], v);                     // streaming: don't pollute L2
            Scu[r * SC_STRIDE + i] = f2tf(v);
        }
    }

    // ---- phase 3: O = w · V ----
    // warp grid: nhalf(2) x kslice(4). Each warp: m16 x n32 over 1/4 of each chunk's K.
    const uint32_t* Scu = reinterpret_cast<const uint32_t*>(Sc);
    const int nhalf  = w & 1;
    const int kslice = w >> 1;          // 0..3
    float acc[4][4];
    #pragma unroll
    for (int nf = 0; nf < 4; nf++)
        #pragma unroll
        for (int e = 0; e < 4; e++) acc[nf][e] = 0.0f;

    for (int c = 0; c < NCH; c++) {
        cp_wait0();
        __syncthreads();   // V chunk c landed; softmax visible (c==0); buffer reuse safe
        if (c + 1 < NCH) issueV(c + 1, (c + 1) & 1);

        const uint32_t* buf = reinterpret_cast<const uint32_t*>(KV + (c & 1) * CHUNK * KV_STRIDE);
        const int cb = c * CHUNK;
        #pragma unroll
        for (int j = 0; j < 2; j++) {                 // 2 ks-steps per kslice (64/8/4)
            const int kk = (kslice * 2 + j) * 8;
            uint32_t af[4];
            af[0] = Scu[gid       * SC_STRIDE + cb + kk + ctid];
            af[1] = Scu[(gid + 8) * SC_STRIDE + cb + kk + ctid];
            af[2] = Scu[gid       * SC_STRIDE + cb + kk + ctid + 4];
            af[3] = Scu[(gid + 8) * SC_STRIDE + cb + kk + ctid + 4];
            #pragma unroll
            for (int nf = 0; nf < 4; nf++) {
                uint32_t bf[2];
                const int col = nhalf * 32 + nf * 8 + gid;
                bf[0] = buf[(kk + ctid)     * KV_STRIDE + col];
                bf[1] = buf[(kk + ctid + 4) * KV_STRIDE + col];
                mma_tf32(acc[nf], af, bf);
            }
        }
    }

    // ---- kslice reduction (reuse Sc region; padded stride 17) ----
    __syncthreads();   // all phase-3 reads of Sc/KV done
    float* red = Sc;
    const int rbase = (w * 32 + lane) * 17;
    #pragma unroll
    for (int nf = 0; nf < 4; nf++)
        #pragma unroll
        for (int e = 0; e < 4; e++) red[rbase + nf * 4 + e] = acc[nf][e];
    __syncthreads();

    if (kslice == 0) {    // warps 0 (nhalf 0) and 1 (nhalf 1) finalize
        #pragma unroll
        for (int nf = 0; nf < 4; nf++)
            #pragma unroll
            for (int e = 0; e < 4; e++)
                acc[nf][e] += red[((w + 2) * 32 + lane) * 17 + nf * 4 + e]
                            + red[((w + 4) * 32 + lane) * 17 + nf * 4 + e]
                            + red[((w + 6) * 32 + lane) * 17 + nf * 4 + e];

        // epilogue: head-merged O, pre-rounded tf32 (feeds output projection)
        const int r0 = qbase + gid;
        #pragma unroll
        for (int nf = 0; nf < 4; nf++) {
            const int c0 = h * HDIM + nhalf * 32 + nf * 8 + 2 * ctid;
            float2 v0 = make_float2(__uint_as_float(f2tf(acc[nf][0])), __uint_as_float(f2tf(acc[nf][1])));
            float2 v1 = make_float2(__uint_as_float(f2tf(acc[nf][2])), __uint_as_float(f2tf(acc[nf][3])));
            *reinterpret_cast<float2*>(&O[((long long)b * Sq + r0) * DHID + c0])     = v0;
            *reinterpret_cast<float2*>(&O[((long long)b * Sq + r0 + 8) * DHID + c0]) = v1;
        }
    }
}

// ---------------- host orchestration ----------------
extern "C" void kernel_launch(void* const* d_in, const int* in_sizes, int n_in,
                              void* d_out, int out_size)
{
    const float* q_text  = (const float*)d_in[0];
    const float* q_image = (const float*)d_in[1];
    const float* k_text  = (const float*)d_in[2];
    const float* k_image = (const float*)d_in[3];
    const float* Wq_t = (const float*)d_in[4];  const float* bq_t = (const float*)d_in[5];
    const float* Wk_t = (const float*)d_in[6];  const float* bk_t = (const float*)d_in[7];
    const float* Wv_t = (const float*)d_in[8];  const float* bv_t = (const float*)d_in[9];
    const float* Wq_i = (const float*)d_in[10]; const float* bq_i = (const float*)d_in[11];
    const float* Wk_i = (const float*)d_in[12]; const float* bk_i = (const float*)d_in[13];
    const float* Wv_i = (const float*)d_in[14]; const float* bv_i = (const float*)d_in[15];
    const float* lng_t = (const float*)d_in[16]; const float* lnb_t = (const float*)d_in[17];
    const float* lng_i = (const float*)d_in[18]; const float* lnb_i = (const float*)d_in[19];
    const float* Wo = (const float*)d_in[20]; const float* bo = (const float*)d_in[21];

    float* out = (float*)d_out;
    const long long OUT_T = 0;
    const long long OUT_I = (long long)BATCH * ST * DHID;
    const long long W_T   = OUT_I + (long long)BATCH * SI * DHID;
    const long long W_I   = W_T + (long long)BATCH * NHEAD * ST * SKV;

    float *pLNQT, *pLNQI, *pLNKT, *pLNKI, *pQT, *pQI, *pK, *pV, *pOT, *pOI, *pWc;
    cudaGetSymbolAddress((void**)&pLNQT, g_ln_qt);
    cudaGetSymbolAddress((void**)&pLNQI, g_ln_qi);
    cudaGetSymbolAddress((void**)&pLNKT, g_ln_kt);
    cudaGetSymbolAddress((void**)&pLNKI, g_ln_ki);
    cudaGetSymbolAddress((void**)&pQT,   g_Q_t);
    cudaGetSymbolAddress((void**)&pQI,   g_Q_i);
    cudaGetSymbolAddress((void**)&pK,    g_K);
    cudaGetSymbolAddress((void**)&pV,    g_V);
    cudaGetSymbolAddress((void**)&pOT,   g_O_t);
    cudaGetSymbolAddress((void**)&pOI,   g_O_i);
    cudaGetSymbolAddress((void**)&pWc,   g_Wc);

    const long long WSZ = (long long)DHID * DHID;
    float* cWq_t = pWc + 0 * WSZ;  float* cWk_t = pWc + 1 * WSZ;  float* cWv_t = pWc + 2 * WSZ;
    float* cWq_i = pWc + 3 * WSZ;  float* cWk_i = pWc + 4 * WSZ;  float* cWv_i = pWc + 5 * WSZ;
    float* cWo   = pWc + 6 * WSZ;

    cudaFuncSetAttribute(gemm_tf32_multi, cudaFuncAttributeMaxDynamicSharedMemorySize, GEMM_SMEM);
    cudaFuncSetAttribute(attn_kernel,     cudaFuncAttributeMaxDynamicSharedMemorySize, ATTN_SMEM);

    // 0) weight pre-round (7 jobs)
    {
        CvtBatch cb;
        cb.j[0] = { Wq_t, cWq_t }; cb.j[1] = { Wk_t, cWk_t }; cb.j[2] = { Wv_t, cWv_t };
        cb.j[3] = { Wq_i, cWq_i }; cb.j[4] = { Wk_i, cWk_i }; cb.j[5] = { Wv_i, cWv_i };
        cb.j[6] = { Wo, cWo };
        cvt_multi<<<dim3(DHID * DHID / (256 * 4), 7), 256>>>(cb);
    }

    // 1) LayerNorms (outputs pre-rounded tf32)
    {
        LnBatch lb;
        lb.j[0] = { q_text,  lng_t, lnb_t, pLNQT, BATCH * ST };
        lb.j[1] = { q_image, lng_i, lnb_i, pLNQI, BATCH * SI };
        lb.j[2] = { k_text,  lng_t, lnb_t, pLNKT, BATCH * ST };
        lb.j[3] = { k_image, lng_i, lnb_i, pLNKI, BATCH * SI };
        ln_multi<<<dim3(BATCH * SI, 4), 256>>>(lb);
    }

    // 2) Projections (one launch, 6 jobs)
    {
        GemmBatch gb;
        gb.j[0] = { pLNQT, cWq_t, pQT, bq_t, BATCH * ST, MODE_QSPLIT, ST, 0,  QSCALE };
        gb.j[1] = { pLNQI, cWq_i, pQI, bq_i, BATCH * SI, MODE_QSPLIT, SI, 0,  QSCALE };
        gb.j[2] = { pLNKT, cWk_t, pK,  bk_t, BATCH * ST, MODE_KV,     ST, 0,  1.0f };
        gb.j[3] = { pLNKI, cWk_i, pK,  bk_i, BATCH * SI, MODE_KV,     SI, ST, 1.0f };
        gb.j[4] = { pLNKT, cWv_t, pV,  bv_t, BATCH * ST, MODE_KV,     ST, 0,  1.0f };
        gb.j[5] = { pLNKI, cWv_i, pV,  bv_i, BATCH * SI, MODE_KV,     SI, ST, 1.0f };
        gemm_tf32_multi<<<dim3(DHID / 128, (BATCH * SI) / 128, 6), 256, GEMM_SMEM>>>(gb);
    }

    // 3) Fused attention (16-row q-tiles, 2 CTAs/SM)
    attn_kernel<<<dim3(ST / QROWS + SI / QROWS, BATCH * NHEAD), 256, ATTN_SMEM>>>(
        pQT, pQI, pK, pV, out + W_T, out + W_I, pOT, pOI);

    // 4) Output projection (one launch, 2 jobs)
    {
        GemmBatch gb;
        gb.j[0] = { pOT, cWo, out + OUT_T, bo, BATCH * ST, MODE_PLAIN, 0, 0, 1.0f };
        gb.j[1] = { pOI, cWo, out + OUT_I, bo, BATCH * SI, MODE_PLAIN, 0, 0, 1.0f };
        gb.j[2] = gb.j[1]; gb.j[3] = gb.j[1]; gb.j[4] = gb.j[1]; gb.j[5] = gb.j[1];
        gemm_tf32_multi<<<dim3(DHID / 128, (BATCH * SI) / 128, 2), 256, GEMM_SMEM>>>(gb);
    }

    (void)in_sizes; (void)n_in; (void)out_size;
}

// round 14
// speedup vs baseline: 1.0092x; 1.0092x over previous
#include <cuda_runtime.h>
#include <cstdint>

#define DHID  1024
#define NHEAD 16
#define HDIM  64
#define BATCH 4
#define ST    512
#define SI    576
#define SKV   1088
#define QSCALE 0.125f
#define LN_EPS 1e-5f

#define Q_STRIDE  68     // Q staging stride, %32==4
#define KV_STRIDE 72     // K/V chunk stride, %32==8

// ---------------- scratch (device globals; allocation-free) ----------------
__device__ float g_ln_qt[BATCH * ST * DHID];
__device__ float g_ln_qi[BATCH * SI * DHID];
__device__ float g_ln_kt[BATCH * ST * DHID];
__device__ float g_ln_ki[BATCH * SI * DHID];
__device__ float g_Q_t[BATCH * NHEAD * ST * HDIM];
__device__ float g_Q_i[BATCH * NHEAD * SI * HDIM];
__device__ float g_K  [BATCH * NHEAD * SKV * HDIM];
__device__ float g_V  [BATCH * NHEAD * SKV * HDIM];
__device__ float g_O_t[BATCH * ST * DHID];
__device__ float g_O_i[BATCH * SI * DHID];
__device__ float g_Wc [7 * DHID * DHID];   // pre-rounded tf32 weights

// ---------------- helpers ----------------
__device__ __forceinline__ uint32_t f2tf(float f) {
    uint32_t u; asm("cvt.rna.tf32.f32 %0, %1;" : "=r"(u) : "f"(f)); return u;
}
__device__ __forceinline__ void mma_tf32(float* d, const uint32_t* a, const uint32_t* b) {
    asm volatile("mma.sync.aligned.m16n8k8.row.col.f32.tf32.tf32.f32 "
                 "{%0,%1,%2,%3}, {%4,%5,%6,%7}, {%8,%9}, {%0,%1,%2,%3};"
                 : "+f"(d[0]), "+f"(d[1]), "+f"(d[2]), "+f"(d[3])
                 : "r"(a[0]), "r"(a[1]), "r"(a[2]), "r"(a[3]), "r"(b[0]), "r"(b[1]));
}
__device__ __forceinline__ uint32_t s2u(const void* p) {
    return (uint32_t)__cvta_generic_to_shared(p);
}
__device__ __forceinline__ void cp16(uint32_t dst, const void* src) {
    asm volatile("cp.async.cg.shared.global [%0], [%1], 16;" :: "r"(dst), "l"(src));
}
__device__ __forceinline__ void cp_commit() {
    asm volatile("cp.async.commit_group;");
}
__device__ __forceinline__ void cp_wait0() {
    asm volatile("cp.async.wait_group 0;" ::: "memory");
}
__device__ __forceinline__ void cp_wait1() {
    asm volatile("cp.async.wait_group 1;" ::: "memory");
}
__device__ __forceinline__ void stg_cs2(float* p, float x, float y) {
    asm volatile("st.global.cs.v2.f32 [%0], {%1, %2};" :: "l"(p), "f"(x), "f"(y));
}

// ---------------- tf32 pre-round for weights (7 jobs, one launch) ----------------
struct CvtJob { const float* in; float* out; };
struct CvtBatch { CvtJob j[7]; };

__global__ __launch_bounds__(256) void cvt_multi(CvtBatch batch)
{
    const CvtJob jb = batch.j[blockIdx.y];
    const int i = blockIdx.x * 256 + threadIdx.x;
    float4 v = reinterpret_cast<const float4*>(jb.in)[i];
    uint4 u = make_uint4(f2tf(v.x), f2tf(v.y), f2tf(v.z), f2tf(v.w));
    reinterpret_cast<uint4*>(jb.out)[i] = u;
}

// ---------------- LayerNorm (4 jobs; output pre-rounded tf32) ----------------
struct LnJob { const float* x; const float* g; const float* b; float* y; int rows; };
struct LnBatch { LnJob j[4]; };

__global__ __launch_bounds__(256) void ln_multi(LnBatch batch)
{
    const LnJob jb = batch.j[blockIdx.y];
    const int row = blockIdx.x;
    if (row >= jb.rows) return;
    const int t = threadIdx.x;
    const float4 xv = reinterpret_cast<const float4*>(jb.x + (long long)row * DHID)[t];

    float s  = xv.x + xv.y + xv.z + xv.w;
    float sq = xv.x * xv.x + xv.y * xv.y + xv.z * xv.z + xv.w * xv.w;

    __shared__ float red_s[8], red_q[8];
    #pragma unroll
    for (int o = 16; o > 0; o >>= 1) {
        s  += __shfl_xor_sync(0xffffffffu, s,  o);
        sq += __shfl_xor_sync(0xffffffffu, sq, o);
    }
    if ((t & 31) == 0) { red_s[t >> 5] = s; red_q[t >> 5] = sq; }
    __syncthreads();
    float ts = red_s[t & 7], tq = red_q[t & 7];
    #pragma unroll
    for (int o = 4; o > 0; o >>= 1) {
        ts += __shfl_xor_sync(0xffffffffu, ts, o);
        tq += __shfl_xor_sync(0xffffffffu, tq, o);
    }
    ts = __shfl_sync(0xffffffffu, ts, 0);
    tq = __shfl_sync(0xffffffffu, tq, 0);

    const float mean = ts * (1.0f / DHID);
    const float rstd = rsqrtf(tq * (1.0f / DHID) - mean * mean + LN_EPS);

    const float4 gv = reinterpret_cast<const float4*>(jb.g)[t];
    const float4 bv = reinterpret_cast<const float4*>(jb.b)[t];
    uint4 o;
    o.x = f2tf((xv.x - mean) * rstd * gv.x + bv.x);
    o.y = f2tf((xv.y - mean) * rstd * gv.y + bv.y);
    o.z = f2tf((xv.z - mean) * rstd * gv.z + bv.z);
    o.w = f2tf((xv.w - mean) * rstd * gv.w + bv.w);
    reinterpret_cast<uint4*>(jb.y + (long long)row * DHID)[t] = o;
}

// ---------------- batched tf32 GEMM (3-stage cp.async; no inner cvt) ----------------
#define MODE_PLAIN  0   // fp32 store (final outputs)
#define MODE_QSPLIT 1   // tf32-rounded store
#define MODE_KV     2   // tf32-rounded store

struct GemmJob {
    const float* A; const float* Bt; float* C; const float* bias;
    int M; int mode; int S; int off; float alpha;
};
struct GemmBatch { GemmJob j[6]; };

#define GSTG (128 * 36)
#define GEMM_SMEM (6 * GSTG * 4)   // 3 stages x (A+B) = 110592 bytes

__global__ __launch_bounds__(256, 2) void gemm_tf32_multi(GemmBatch batch)
{
    extern __shared__ float smem[];
    const GemmJob jb = batch.j[blockIdx.z];
    const int bm = blockIdx.y * 128;
    if (bm >= jb.M) return;
    const int bn = blockIdx.x * 128;

    const int tid  = threadIdx.x;
    const int w    = tid >> 5;
    const int lane = tid & 31;
    const int gid  = lane >> 2;
    const int ctid = lane & 3;
    const int wm = (w & 1) * 64;
    const int wn = (w >> 1) * 32;
    const int lr = tid >> 3;
    const int lc = (tid & 7) * 4;

    const float* A  = jb.A;
    const float* Bt = jb.Bt;

    auto issue = [&](int k0, int s) {
        float* as = smem + s * 2 * GSTG;
        float* bs = as + GSTG;
        #pragma unroll
        for (int p = 0; p < 4; p++) {
            cp16(s2u(&as[(lr + p * 32) * 36 + lc]), &A [(long long)(bm + lr + p * 32) * DHID + k0 + lc]);
            cp16(s2u(&bs[(lr + p * 32) * 36 + lc]), &Bt[(long long)(bn + lr + p * 32) * DHID + k0 + lc]);
        }
        cp_commit();
    };

    float acc[4][4][4];
    #pragma unroll
    for (int i = 0; i < 4; i++)
        #pragma unroll
        for (int j = 0; j < 4; j++)
            #pragma unroll
            for (int e = 0; e < 4; e++) acc[i][j][e] = 0.0f;

    issue(0, 0);
    issue(32, 1);

    for (int it = 0; it < 32; it++) {
        if (it == 31) cp_wait0(); else cp_wait1();   // tail-aware drain
        __syncthreads();
        if (it + 2 < 32) issue((it + 2) * 32, (it + 2) % 3);

        const uint32_t* as = reinterpret_cast<const uint32_t*>(smem + (it % 3) * 2 * GSTG);
        const uint32_t* bs = as + GSTG;

        #pragma unroll
        for (int ks = 0; ks < 4; ks++) {
            const int kk = ks * 8;
            uint32_t af[4][4], bf[4][2];
            #pragma unroll
            for (int mf = 0; mf < 4; mf++) {
                const int r = wm + mf * 16 + gid;
                af[mf][0] = as[r       * 36 + kk + ctid];
                af[mf][1] = as[(r + 8) * 36 + kk + ctid];
                af[mf][2] = as[r       * 36 + kk + ctid + 4];
                af[mf][3] = as[(r + 8) * 36 + kk + ctid + 4];
            }
            #pragma unroll
            for (int nf = 0; nf < 4; nf++) {
                const int c = wn + nf * 8 + gid;
                bf[nf][0] = bs[c * 36 + kk + ctid];
                bf[nf][1] = bs[c * 36 + kk + ctid + 4];
            }
            #pragma unroll
            for (int mf = 0; mf < 4; mf++)
                #pragma unroll
                for (int nf = 0; nf < 4; nf++)
                    mma_tf32(acc[mf][nf], af[mf], bf[nf]);
        }
    }

    const bool rnd = (jb.mode != MODE_PLAIN);
    #pragma unroll
    for (int mf = 0; mf < 4; mf++) {
        #pragma unroll
        for (int nf = 0; nf < 4; nf++) {
            const int r0 = bm + wm + mf * 16 + gid;
            const int c0 = bn + wn + nf * 8 + 2 * ctid;
            const float b0 = jb.bias ? jb.bias[c0]     : 0.0f;
            const float b1 = jb.bias ? jb.bias[c0 + 1] : 0.0f;
            float v00 = (acc[mf][nf][0] + b0) * jb.alpha;
            float v01 = (acc[mf][nf][1] + b1) * jb.alpha;
            float v10 = (acc[mf][nf][2] + b0) * jb.alpha;
            float v11 = (acc[mf][nf][3] + b1) * jb.alpha;
            if (rnd) {
                v00 = __uint_as_float(f2tf(v00)); v01 = __uint_as_float(f2tf(v01));
                v10 = __uint_as_float(f2tf(v10)); v11 = __uint_as_float(f2tf(v11));
            }
            long long i0, i1;
            if (jb.mode == MODE_PLAIN) {
                i0 = (long long)r0 * DHID + c0;
                i1 = (long long)(r0 + 8) * DHID + c0;
            } else {
                const int h  = c0 >> 6, hd = c0 & 63;
                const int b_  = r0 / jb.S, s0 = r0 - b_ * jb.S;
                const int b_2 = (r0 + 8) / jb.S, s1 = (r0 + 8) - b_2 * jb.S;
                if (jb.mode == MODE_QSPLIT) {
                    i0 = (((long long)(b_  * NHEAD + h)) * jb.S + s0) * HDIM + hd;
                    i1 = (((long long)(b_2 * NHEAD + h)) * jb.S + s1) * HDIM + hd;
                } else {
                    i0 = (((long long)(b_  * NHEAD + h)) * SKV + jb.off + s0) * HDIM + hd;
                    i1 = (((long long)(b_2 * NHEAD + h)) * SKV + jb.off + s1) * HDIM + hd;
                }
            }
            *reinterpret_cast<float2*>(&jb.C[i0]) = make_float2(v00, v01);
            *reinterpret_cast<float2*>(&jb.C[i1]) = make_float2(v10, v11);
        }
    }
}

// ---------------- scores kernel: Q·Kᵀ + softmax + w write, scores in REGISTERS ----
// 512 threads, 32 q-rows per block. Score fragments live in sacc[9][2][4] regs.
// smem = Q (8.7KB) + K double buffer (73.7KB) + reduce scratch (2.2KB) ≈ 84.6KB -> 2 CTAs/SM.
#define SCHUNK 128
#define SNCH 9                      // ceil(1088/128); last chunk = 64 cols
#define SCORES_SMEM ((32 * Q_STRIDE + 2 * SCHUNK * KV_STRIDE + 32 * 16 + 32) * 4)

__global__ __launch_bounds__(512, 2) void scores_kernel(
    const float* __restrict__ Qt, const float* __restrict__ Qi,
    const float* __restrict__ Kg,
    float* __restrict__ Wt, float* __restrict__ Wi)
{
    extern __shared__ float smf[];
    float* Qs      = smf;                                  // 32 x Q_STRIDE
    float* KV      = Qs + 32 * Q_STRIDE;                   // 2 x SCHUNK x KV_STRIDE
    float* red     = KV + 2 * SCHUNK * KV_STRIDE;          // 32 x 16
    float* rowstat = red + 32 * 16;                        // 32

    const bool isT = blockIdx.x < (ST / 32);
    const int  Sq  = isT ? ST : SI;
    const float* Q   = isT ? Qt : Qi;
    float* Wout      = isT ? Wt : Wi;
    const int qbase  = (isT ? blockIdx.x : blockIdx.x - ST / 32) * 32;

    const int z = blockIdx.y;
    const int tid  = threadIdx.x;
    const int w    = tid >> 5;          // 0..15
    const int lane = tid & 31;
    const int gid  = lane >> 2;
    const int ctid = lane & 3;

    auto issueK = [&](int c, int s) {
        float* dst = KV + s * SCHUNK * KV_STRIDE;
        const int rows = (c == SNCH - 1) ? (SKV - c * SCHUNK) : SCHUNK;
        for (int i = tid; i < rows * 16; i += 512) {
            const int r = i >> 4, c4 = (i & 15) * 4;
            cp16(s2u(&dst[r * KV_STRIDE + c4]), &Kg[((long long)z * SKV + c * SCHUNK + r) * HDIM + c4]);
        }
        cp_commit();
    };

    // group 0: Q + K chunk 0
    for (int i = tid; i < 32 * 16; i += 512) {
        const int r = i >> 4, c4 = (i & 15) * 4;
        cp16(s2u(&Qs[r * Q_STRIDE + c4]), &Q[((long long)z * Sq + qbase + r) * HDIM + c4]);
    }
    issueK(0, 0);
    cp_wait0();
    __syncthreads();

    // hoist Q fragments (pre-rounded tf32 -> raw loads)
    const uint32_t* Qsu = reinterpret_cast<const uint32_t*>(Qs);
    uint32_t qf[8][2][4];
    #pragma unroll
    for (int ks = 0; ks < 8; ks++) {
        const int kk = ks * 8;
        #pragma unroll
        for (int mf = 0; mf < 2; mf++) {
            const int r = mf * 16 + gid;
            qf[ks][mf][0] = Qsu[r       * Q_STRIDE + kk + ctid];
            qf[ks][mf][1] = Qsu[(r + 8) * Q_STRIDE + kk + ctid];
            qf[ks][mf][2] = Qsu[r       * Q_STRIDE + kk + ctid + 4];
            qf[ks][mf][3] = Qsu[(r + 8) * Q_STRIDE + kk + ctid + 4];
        }
    }

    // ---- phase 1: scores into registers ----
    // thread covers rows {gid, gid+8, gid+16, gid+24}, cols {c*128 + w*8 + 2ctid, +1}
    float sacc[SNCH][2][4];
    #pragma unroll
    for (int c = 0; c < SNCH; c++) {
        if (c > 0) { cp_wait0(); __syncthreads(); }
        if (c + 1 < SNCH) issueK(c + 1, (c + 1) & 1);

        const int cw = (c == SNCH - 1) ? (SKV - c * SCHUNK) : SCHUNK;
        const uint32_t* buf = reinterpret_cast<const uint32_t*>(KV + (c & 1) * SCHUNK * KV_STRIDE);
        if (w * 8 < cw) {
            #pragma unroll
            for (int mf = 0; mf < 2; mf++)
                #pragma unroll
                for (int e = 0; e < 4; e++) sacc[c][mf][e] = 0.0f;

            const int col = w * 8 + gid;
            #pragma unroll
            for (int ks = 0; ks < 8; ks++) {
                const int kk = ks * 8;
                uint32_t bf[2];
                bf[0] = buf[col * KV_STRIDE + kk + ctid];
                bf[1] = buf[col * KV_STRIDE + kk + ctid + 4];
                mma_tf32(sacc[c][0], qf[ks][0], bf);
                mma_tf32(sacc[c][1], qf[ks][1], bf);
            }
        }
    }
    const bool tailAct = (w < 8);   // warps 8..15 have no chunk-8 columns

    // ---- row max ----
    float pm[4] = {-1e30f, -1e30f, -1e30f, -1e30f};
    #pragma unroll
    for (int c = 0; c < SNCH - 1; c++) {
        pm[0] = fmaxf(pm[0], fmaxf(sacc[c][0][0], sacc[c][0][1]));
        pm[1] = fmaxf(pm[1], fmaxf(sacc[c][0][2], sacc[c][0][3]));
        pm[2] = fmaxf(pm[2], fmaxf(sacc[c][1][0], sacc[c][1][1]));
        pm[3] = fmaxf(pm[3], fmaxf(sacc[c][1][2], sacc[c][1][3]));
    }
    if (tailAct) {
        pm[0] = fmaxf(pm[0], fmaxf(sacc[SNCH-1][0][0], sacc[SNCH-1][0][1]));
        pm[1] = fmaxf(pm[1], fmaxf(sacc[SNCH-1][0][2], sacc[SNCH-1][0][3]));
        pm[2] = fmaxf(pm[2], fmaxf(sacc[SNCH-1][1][0], sacc[SNCH-1][1][1]));
        pm[3] = fmaxf(pm[3], fmaxf(sacc[SNCH-1][1][2], sacc[SNCH-1][1][3]));
    }
    #pragma unroll
    for (int j = 0; j < 4; j++) {
        pm[j] = fmaxf(pm[j], __shfl_xor_sync(0xffffffffu, pm[j], 1));
        pm[j] = fmaxf(pm[j], __shfl_xor_sync(0xffffffffu, pm[j], 2));
    }
    if (ctid == 0) {
        red[gid        * 16 + w] = pm[0];
        red[(gid + 8)  * 16 + w] = pm[1];
        red[(gid + 16) * 16 + w] = pm[2];
        red[(gid + 24) * 16 + w] = pm[3];
    }
    __syncthreads();
    if (tid < 32) {
        float m = red[tid * 16];
        #pragma unroll
        for (int i = 1; i < 16; i++) m = fmaxf(m, red[tid * 16 + i]);
        rowstat[tid] = m;
    }
    __syncthreads();
    const float m0 = rowstat[gid], m1 = rowstat[gid + 8];
    const float m2 = rowstat[gid + 16], m3 = rowstat[gid + 24];

    // ---- exp in regs + row sum ----
    float ps[4] = {0.0f, 0.0f, 0.0f, 0.0f};
    #pragma unroll
    for (int c = 0; c < SNCH - 1; c++) {
        sacc[c][0][0] = __expf(sacc[c][0][0] - m0); ps[0] += sacc[c][0][0];
        sacc[c][0][1] = __expf(sacc[c][0][1] - m0); ps[0] += sacc[c][0][1];
        sacc[c][0][2] = __expf(sacc[c][0][2] - m1); ps[1] += sacc[c][0][2];
        sacc[c][0][3] = __expf(sacc[c][0][3] - m1); ps[1] += sacc[c][0][3];
        sacc[c][1][0] = __expf(sacc[c][1][0] - m2); ps[2] += sacc[c][1][0];
        sacc[c][1][1] = __expf(sacc[c][1][1] - m2); ps[2] += sacc[c][1][1];
        sacc[c][1][2] = __expf(sacc[c][1][2] - m3); ps[3] += sacc[c][1][2];
        sacc[c][1][3] = __expf(sacc[c][1][3] - m3); ps[3] += sacc[c][1][3];
    }
    if (tailAct) {
        const int c = SNCH - 1;
        sacc[c][0][0] = __expf(sacc[c][0][0] - m0); ps[0] += sacc[c][0][0];
        sacc[c][0][1] = __expf(sacc[c][0][1] - m0); ps[0] += sacc[c][0][1];
        sacc[c][0][2] = __expf(sacc[c][0][2] - m1); ps[1] += sacc[c][0][2];
        sacc[c][0][3] = __expf(sacc[c][0][3] - m1); ps[1] += sacc[c][0][3];
        sacc[c][1][0] = __expf(sacc[c][1][0] - m2); ps[2] += sacc[c][1][0];
        sacc[c][1][1] = __expf(sacc[c][1][1] - m2); ps[2] += sacc[c][1][1];
        sacc[c][1][2] = __expf(sacc[c][1][2] - m3); ps[3] += sacc[c][1][2];
        sacc[c][1][3] = __expf(sacc[c][1][3] - m3); ps[3] += sacc[c][1][3];
    }
    #pragma unroll
    for (int j = 0; j < 4; j++) {
        ps[j] += __shfl_xor_sync(0xffffffffu, ps[j], 1);
        ps[j] += __shfl_xor_sync(0xffffffffu, ps[j], 2);
    }
    __syncthreads();   // rowstat reads done before red reuse below overwrites flow
    if (ctid == 0) {
        red[gid        * 16 + w] = ps[0];
        red[(gid + 8)  * 16 + w] = ps[1];
        red[(gid + 16) * 16 + w] = ps[2];
        red[(gid + 24) * 16 + w] = ps[3];
    }
    __syncthreads();
    if (tid < 32) {
        float s = red[tid * 16];
        #pragma unroll
        for (int i = 1; i < 16; i++) s += red[tid * 16 + i];
        rowstat[tid] = 1.0f / s;
    }
    __syncthreads();
    const float i0 = rowstat[gid], i1 = rowstat[gid + 8];
    const float i2 = rowstat[gid + 16], i3 = rowstat[gid + 24];

    // ---- w write from registers (streaming stores; 4x8B per 32B sector) ----
    float* base = Wout + ((long long)z * Sq + qbase) * SKV;
    #pragma unroll
    for (int c = 0; c < SNCH - 1; c++) {
        const int c0 = c * SCHUNK + w * 8 + 2 * ctid;
        stg_cs2(base + (gid)        * SKV + c0, sacc[c][0][0] * i0, sacc[c][0][1] * i0);
        stg_cs2(base + (gid + 8)  * SKV + c0, sacc[c][0][2] * i1, sacc[c][0][3] * i1);
        stg_cs2(base + (gid + 16) * SKV + c0, sacc[c][1][0] * i2, sacc[c][1][1] * i2);
        stg_cs2(base + (gid + 24) * SKV + c0, sacc[c][1][2] * i3, sacc[c][1][3] * i3);
    }
    if (tailAct) {
        const int c = SNCH - 1;
        const int c0 = c * SCHUNK + w * 8 + 2 * ctid;
        stg_cs2(base + (gid)        * SKV + c0, sacc[c][0][0] * i0, sacc[c][0][1] * i0);
        stg_cs2(base + (gid + 8)  * SKV + c0, sacc[c][0][2] * i1, sacc[c][0][3] * i1);
        stg_cs2(base + (gid + 16) * SKV + c0, sacc[c][1][0] * i2, sacc[c][1][1] * i2);
        stg_cs2(base + (gid + 24) * SKV + c0, sacc[c][1][2] * i3, sacc[c][1][3] * i3);
    }
}

// ---------------- AV kernel: O = w · V (batched 128x64x1088 tf32 GEMM) ----------------
// A = w rows [Sq][1088] per z (fp32, cvt'd per fragment); B = V [kv][hd] read transposed.
#define AV_ASTG (128 * 36)
#define AV_BSTG (32 * KV_STRIDE)
#define AV_STG  (AV_ASTG + AV_BSTG)
#define AV_SMEM (3 * AV_STG * 4)      // 82944 bytes
#define AV_NKIT (SKV / 32)            // 34

__global__ __launch_bounds__(256, 2) void av_kernel(
    const float* __restrict__ Wt, const float* __restrict__ Wi,
    const float* __restrict__ Vg,
    float* __restrict__ Ot, float* __restrict__ Oi)
{
    extern __shared__ float smem[];
    const int mt = blockIdx.y;           // 0..3 text, 4..8 image
    const bool isT = mt < 4;
    const int Sq = isT ? ST : SI;
    const float* Wsrc = isT ? Wt : Wi;
    float* O = isT ? Ot : Oi;
    const int bm = (isT ? mt : mt - 4) * 128;
    const int z = blockIdx.z;
    const int b = z >> 4, h = z & 15;
    const float* A = Wsrc + (long long)z * Sq * SKV;
    const float* V = Vg + (long long)z * SKV * HDIM;

    const int tid  = threadIdx.x;
    const int w    = tid >> 5;
    const int lane = tid & 31;
    const int gid  = lane >> 2;
    const int ctid = lane & 3;
    const int wm = (w & 1) * 64;
    const int wn = (w >> 1) * 16;

    const int lrA = tid >> 3, lcA = (tid & 7) * 4;
    const int lrB = tid >> 4, lcB = (tid & 15) * 4;

    auto issue = [&](int k0, int s) {
        float* as = smem + s * AV_STG;
        float* bs = as + AV_ASTG;
        #pragma unroll
        for (int p = 0; p < 4; p++) {
            int ar = bm + lrA + p * 32;
            if (ar >= Sq) ar = Sq - 1;          // clamp (dup rows; stores guarded)
            cp16(s2u(&as[(lrA + p * 32) * 36 + lcA]), &A[(long long)ar * SKV + k0 + lcA]);
        }
        #pragma unroll
        for (int p = 0; p < 2; p++) {
            cp16(s2u(&bs[(lrB + p * 16) * KV_STRIDE + lcB]), &V[(long long)(k0 + lrB + p * 16) * HDIM + lcB]);
        }
        cp_commit();
    };

    float acc[4][2][4];
    #pragma unroll
    for (int i = 0; i < 4; i++)
        #pragma unroll
        for (int j = 0; j < 2; j++)
            #pragma unroll
            for (int e = 0; e < 4; e++) acc[i][j][e] = 0.0f;

    issue(0, 0);
    issue(32, 1);

    for (int it = 0; it < AV_NKIT; it++) {
        if (it == AV_NKIT - 1) cp_wait0(); else cp_wait1();
        __syncthreads();
        if (it + 2 < AV_NKIT) issue((it + 2) * 32, (it + 2) % 3);

        const float*    as = smem + (it % 3) * AV_STG;
        const uint32_t* bs = reinterpret_cast<const uint32_t*>(as + AV_ASTG);

        #pragma unroll
        for (int ks = 0; ks < 4; ks++) {
            const int kk = ks * 8;
            uint32_t af[4][4], bf[2][2];
            #pragma unroll
            for (int mf = 0; mf < 4; mf++) {
                const int r = wm + mf * 16 + gid;
                af[mf][0] = f2tf(as[r       * 36 + kk + ctid]);
                af[mf][1] = f2tf(as[(r + 8) * 36 + kk + ctid]);
                af[mf][2] = f2tf(as[r       * 36 + kk + ctid + 4]);
                af[mf][3] = f2tf(as[(r + 8) * 36 + kk + ctid + 4]);
            }
            #pragma unroll
            for (int nf = 0; nf < 2; nf++) {
                const int col = wn + nf * 8 + gid;
                bf[nf][0] = bs[(kk + ctid)     * KV_STRIDE + col];
                bf[nf][1] = bs[(kk + ctid + 4) * KV_STRIDE + col];
            }
            #pragma unroll
            for (int mf = 0; mf < 4; mf++)
                #pragma unroll
                for (int nf = 0; nf < 2; nf++)
                    mma_tf32(acc[mf][nf], af[mf], bf[nf]);
        }
    }

    // epilogue: head-merged O, tf32-rounded (feeds output projection); row-guarded
    #pragma unroll
    for (int mf = 0; mf < 4; mf++) {
        #pragma unroll
        for (int nf = 0; nf < 2; nf++) {
            const int r0 = bm + wm + mf * 16 + gid;
            const int c0 = h * HDIM + wn + nf * 8 + 2 * ctid;
            if (r0 < Sq) {
                float2 v = make_float2(__uint_as_float(f2tf(acc[mf][nf][0])),
                                       __uint_as_float(f2tf(acc[mf][nf][1])));
                *reinterpret_cast<float2*>(&O[((long long)b * Sq + r0) * DHID + c0]) = v;
            }
            if (r0 + 8 < Sq) {
                float2 v = make_float2(__uint_as_float(f2tf(acc[mf][nf][2])),
                                       __uint_as_float(f2tf(acc[mf][nf][3])));
                *reinterpret_cast<float2*>(&O[((long long)b * Sq + r0 + 8) * DHID + c0]) = v;
            }
        }
    }
}

// ---------------- host orchestration ----------------
extern "C" void kernel_launch(void* const* d_in, const int* in_sizes, int n_in,
                              void* d_out, int out_size)
{
    const float* q_text  = (const float*)d_in[0];
    const float* q_image = (const float*)d_in[1];
    const float* k_text  = (const float*)d_in[2];
    const float* k_image = (const float*)d_in[3];
    const float* Wq_t = (const float*)d_in[4];  const float* bq_t = (const float*)d_in[5];
    const float* Wk_t = (const float*)d_in[6];  const float* bk_t = (const float*)d_in[7];
    const float* Wv_t = (const float*)d_in[8];  const float* bv_t = (const float*)d_in[9];
    const float* Wq_i = (const float*)d_in[10]; const float* bq_i = (const float*)d_in[11];
    const float* Wk_i = (const float*)d_in[12]; const float* bk_i = (const float*)d_in[13];
    const float* Wv_i = (const float*)d_in[14]; const float* bv_i = (const float*)d_in[15];
    const float* lng_t = (const float*)d_in[16]; const float* lnb_t = (const float*)d_in[17];
    const float* lng_i = (const float*)d_in[18]; const float* lnb_i = (const float*)d_in[19];
    const float* Wo = (const float*)d_in[20]; const float* bo = (const float*)d_in[21];

    float* out = (float*)d_out;
    const long long OUT_T = 0;
    const long long OUT_I = (long long)BATCH * ST * DHID;
    const long long W_T   = OUT_I + (long long)BATCH * SI * DHID;
    const long long W_I   = W_T + (long long)BATCH * NHEAD * ST * SKV;

    float *pLNQT, *pLNQI, *pLNKT, *pLNKI, *pQT, *pQI, *pK, *pV, *pOT, *pOI, *pWc;
    cudaGetSymbolAddress((void**)&pLNQT, g_ln_qt);
    cudaGetSymbolAddress((void**)&pLNQI, g_ln_qi);
    cudaGetSymbolAddress((void**)&pLNKT, g_ln_kt);
    cudaGetSymbolAddress((void**)&pLNKI, g_ln_ki);
    cudaGetSymbolAddress((void**)&pQT,   g_Q_t);
    cudaGetSymbolAddress((void**)&pQI,   g_Q_i);
    cudaGetSymbolAddress((void**)&pK,    g_K);
    cudaGetSymbolAddress((void**)&pV,    g_V);
    cudaGetSymbolAddress((void**)&pOT,   g_O_t);
    cudaGetSymbolAddress((void**)&pOI,   g_O_i);
    cudaGetSymbolAddress((void**)&pWc,   g_Wc);

    const long long WSZ = (long long)DHID * DHID;
    float* cWq_t = pWc + 0 * WSZ;  float* cWk_t = pWc + 1 * WSZ;  float* cWv_t = pWc + 2 * WSZ;
    float* cWq_i = pWc + 3 * WSZ;  float* cWk_i = pWc + 4 * WSZ;  float* cWv_i = pWc + 5 * WSZ;
    float* cWo   = pWc + 6 * WSZ;

    cudaFuncSetAttribute(gemm_tf32_multi, cudaFuncAttributeMaxDynamicSharedMemorySize, GEMM_SMEM);
    cudaFuncSetAttribute(scores_kernel,   cudaFuncAttributeMaxDynamicSharedMemorySize, SCORES_SMEM);
    cudaFuncSetAttribute(av_kernel,       cudaFuncAttributeMaxDynamicSharedMemorySize, AV_SMEM);

    // 0) weight pre-round (7 jobs)
    {
        CvtBatch cb;
        cb.j[0] = { Wq_t, cWq_t }; cb.j[1] = { Wk_t, cWk_t }; cb.j[2] = { Wv_t, cWv_t };
        cb.j[3] = { Wq_i, cWq_i }; cb.j[4] = { Wk_i, cWk_i }; cb.j[5] = { Wv_i, cWv_i };
        cb.j[6] = { Wo, cWo };
        cvt_multi<<<dim3(DHID * DHID / (256 * 4), 7), 256>>>(cb);
    }

    // 1) LayerNorms (outputs pre-rounded tf32)
    {
        LnBatch lb;
        lb.j[0] = { q_text,  lng_t, lnb_t, pLNQT, BATCH * ST };
        lb.j[1] = { q_image, lng_i, lnb_i, pLNQI, BATCH * SI };
        lb.j[2] = { k_text,  lng_t, lnb_t, pLNKT, BATCH * ST };
        lb.j[3] = { k_image, lng_i, lnb_i, pLNKI, BATCH * SI };
        ln_multi<<<dim3(BATCH * SI, 4), 256>>>(lb);
    }

    // 2) Projections (one launch, 6 jobs)
    {
        GemmBatch gb;
        gb.j[0] = { pLNQT, cWq_t, pQT, bq_t, BATCH * ST, MODE_QSPLIT, ST, 0,  QSCALE };
        gb.j[1] = { pLNQI, cWq_i, pQI, bq_i, BATCH * SI, MODE_QSPLIT, SI, 0,  QSCALE };
        gb.j[2] = { pLNKT, cWk_t, pK,  bk_t, BATCH * ST, MODE_KV,     ST, 0,  1.0f };
        gb.j[3] = { pLNKI, cWk_i, pK,  bk_i, BATCH * SI, MODE_KV,     SI, ST, 1.0f };
        gb.j[4] = { pLNKT, cWv_t, pV,  bv_t, BATCH * ST, MODE_KV,     ST, 0,  1.0f };
        gb.j[5] = { pLNKI, cWv_i, pV,  bv_i, BATCH * SI, MODE_KV,     SI, ST, 1.0f };
        gemm_tf32_multi<<<dim3(DHID / 128, (BATCH * SI) / 128, 6), 256, GEMM_SMEM>>>(gb);
    }

    // 3) Scores + softmax + w (register-resident scores, 2 CTAs/SM)
    scores_kernel<<<dim3(ST / 32 + SI / 32, BATCH * NHEAD), 512, SCORES_SMEM>>>(
        pQT, pQI, pK, out + W_T, out + W_I);

    // 4) O = w · V (batched GEMM, 2 CTAs/SM)
    av_kernel<<<dim3(1, 9, BATCH * NHEAD), 256, AV_SMEM>>>(
        out + W_T, out + W_I, pV, pOT, pOI);

    // 5) Output projection (one launch, 2 jobs)
    {
        GemmBatch gb;
        gb.j[0] = { pOT, cWo, out + OUT_T, bo, BATCH * ST, MODE_PLAIN, 0, 0, 1.0f };
        gb.j[1] = { pOI, cWo, out + OUT_I, bo, BATCH * SI, MODE_PLAIN, 0, 0, 1.0f };
        gb.j[2] = gb.j[1]; gb.j[3] = gb.j[1]; gb.j[4] = gb.j[1]; gb.j[5] = gb.j[1];
        gemm_tf32_multi<<<dim3(DHID / 128, (BATCH * SI) / 128, 2), 256, GEMM_SMEM>>>(gb);
    }

    (void)in_sizes; (void)n_in; (void)out_size;
}

// round 15
// speedup vs baseline: 1.1693x; 1.1586x over previous
#include <cuda_runtime.h>
#include <cstdint>

#define DHID  1024
#define NHEAD 16
#define HDIM  64
#define BATCH 4
#define ST    512
#define SI    576
#define SKV   1088
#define QSCALE 0.125f
#define LN_EPS 1e-5f

#define Q_STRIDE  68     // Q staging stride, %32==4
#define KV_STRIDE 72     // K/V chunk stride, %32==8

// ---------------- scratch (device globals; allocation-free) ----------------
__device__ float g_ln_qt[BATCH * ST * DHID];
__device__ float g_ln_qi[BATCH * SI * DHID];
__device__ float g_ln_kt[BATCH * ST * DHID];
__device__ float g_ln_ki[BATCH * SI * DHID];
__device__ float g_Q_t[BATCH * NHEAD * ST * HDIM];
__device__ float g_Q_i[BATCH * NHEAD * SI * HDIM];
__device__ float g_K  [BATCH * NHEAD * SKV * HDIM];
__device__ float g_V  [BATCH * NHEAD * SKV * HDIM];
__device__ float g_O_t[BATCH * ST * DHID];
__device__ float g_O_i[BATCH * SI * DHID];
__device__ float g_Wc [7 * DHID * DHID];   // pre-rounded tf32 weights

// ---------------- helpers ----------------
__device__ __forceinline__ uint32_t f2tf(float f) {
    uint32_t u; asm("cvt.rna.tf32.f32 %0, %1;" : "=r"(u) : "f"(f)); return u;
}
__device__ __forceinline__ void mma_tf32(float* d, const uint32_t* a, const uint32_t* b) {
    asm volatile("mma.sync.aligned.m16n8k8.row.col.f32.tf32.tf32.f32 "
                 "{%0,%1,%2,%3}, {%4,%5,%6,%7}, {%8,%9}, {%0,%1,%2,%3};"
                 : "+f"(d[0]), "+f"(d[1]), "+f"(d[2]), "+f"(d[3])
                 : "r"(a[0]), "r"(a[1]), "r"(a[2]), "r"(a[3]), "r"(b[0]), "r"(b[1]));
}
__device__ __forceinline__ uint32_t s2u(const void* p) {
    return (uint32_t)__cvta_generic_to_shared(p);
}
__device__ __forceinline__ void cp16(uint32_t dst, const void* src) {
    asm volatile("cp.async.cg.shared.global [%0], [%1], 16;" :: "r"(dst), "l"(src));
}
__device__ __forceinline__ void cp_commit() {
    asm volatile("cp.async.commit_group;");
}
__device__ __forceinline__ void cp_wait0() {
    asm volatile("cp.async.wait_group 0;" ::: "memory");
}
__device__ __forceinline__ void cp_wait1() {
    asm volatile("cp.async.wait_group 1;" ::: "memory");
}
__device__ __forceinline__ void stg_cs2(float* p, float x, float y) {
    asm volatile("st.global.cs.v2.f32 [%0], {%1, %2};" :: "l"(p), "f"(x), "f"(y));
}

// ---------------- tf32 pre-round for weights (7 jobs, one launch) ----------------
struct CvtJob { const float* in; float* out; };
struct CvtBatch { CvtJob j[7]; };

__global__ __launch_bounds__(256) void cvt_multi(CvtBatch batch)
{
    const CvtJob jb = batch.j[blockIdx.y];
    const int i = blockIdx.x * 256 + threadIdx.x;
    float4 v = reinterpret_cast<const float4*>(jb.in)[i];
    uint4 u = make_uint4(f2tf(v.x), f2tf(v.y), f2tf(v.z), f2tf(v.w));
    reinterpret_cast<uint4*>(jb.out)[i] = u;
}

// ---------------- LayerNorm (4 jobs; output pre-rounded tf32) ----------------
struct LnJob { const float* x; const float* g; const float* b; float* y; int rows; };
struct LnBatch { LnJob j[4]; };

__global__ __launch_bounds__(256) void ln_multi(LnBatch batch)
{
    const LnJob jb = batch.j[blockIdx.y];
    const int row = blockIdx.x;
    if (row >= jb.rows) return;
    const int t = threadIdx.x;
    const float4 xv = reinterpret_cast<const float4*>(jb.x + (long long)row * DHID)[t];

    float s  = xv.x + xv.y + xv.z + xv.w;
    float sq = xv.x * xv.x + xv.y * xv.y + xv.z * xv.z + xv.w * xv.w;

    __shared__ float red_s[8], red_q[8];
    #pragma unroll
    for (int o = 16; o > 0; o >>= 1) {
        s  += __shfl_xor_sync(0xffffffffu, s,  o);
        sq += __shfl_xor_sync(0xffffffffu, sq, o);
    }
    if ((t & 31) == 0) { red_s[t >> 5] = s; red_q[t >> 5] = sq; }
    __syncthreads();
    float ts = red_s[t & 7], tq = red_q[t & 7];
    #pragma unroll
    for (int o = 4; o > 0; o >>= 1) {
        ts += __shfl_xor_sync(0xffffffffu, ts, o);
        tq += __shfl_xor_sync(0xffffffffu, tq, o);
    }
    ts = __shfl_sync(0xffffffffu, ts, 0);
    tq = __shfl_sync(0xffffffffu, tq, 0);

    const float mean = ts * (1.0f / DHID);
    const float rstd = rsqrtf(tq * (1.0f / DHID) - mean * mean + LN_EPS);

    const float4 gv = reinterpret_cast<const float4*>(jb.g)[t];
    const float4 bv = reinterpret_cast<const float4*>(jb.b)[t];
    uint4 o;
    o.x = f2tf((xv.x - mean) * rstd * gv.x + bv.x);
    o.y = f2tf((xv.y - mean) * rstd * gv.y + bv.y);
    o.z = f2tf((xv.z - mean) * rstd * gv.z + bv.z);
    o.w = f2tf((xv.w - mean) * rstd * gv.w + bv.w);
    reinterpret_cast<uint4*>(jb.y + (long long)row * DHID)[t] = o;
}

// ---------------- batched tf32 GEMM (3-stage cp.async; no inner cvt) ----------------
#define MODE_PLAIN  0   // fp32 store (final outputs)
#define MODE_QSPLIT 1   // tf32-rounded store
#define MODE_KV     2   // tf32-rounded store

struct GemmJob {
    const float* A; const float* Bt; float* C; const float* bias;
    int M; int mode; int S; int off; float alpha;
};
struct GemmBatch { GemmJob j[6]; };

#define GSTG (128 * 36)
#define GEMM_SMEM (6 * GSTG * 4)   // 3 stages x (A+B) = 110592 bytes

__global__ __launch_bounds__(256, 2) void gemm_tf32_multi(GemmBatch batch)
{
    extern __shared__ float smem[];
    const GemmJob jb = batch.j[blockIdx.z];
    const int bm = blockIdx.y * 128;
    if (bm >= jb.M) return;
    const int bn = blockIdx.x * 128;

    const int tid  = threadIdx.x;
    const int w    = tid >> 5;
    const int lane = tid & 31;
    const int gid  = lane >> 2;
    const int ctid = lane & 3;
    const int wm = (w & 1) * 64;
    const int wn = (w >> 1) * 32;
    const int lr = tid >> 3;
    const int lc = (tid & 7) * 4;

    const float* A  = jb.A;
    const float* Bt = jb.Bt;

    auto issue = [&](int k0, int s) {
        float* as = smem + s * 2 * GSTG;
        float* bs = as + GSTG;
        #pragma unroll
        for (int p = 0; p < 4; p++) {
            cp16(s2u(&as[(lr + p * 32) * 36 + lc]), &A [(long long)(bm + lr + p * 32) * DHID + k0 + lc]);
            cp16(s2u(&bs[(lr + p * 32) * 36 + lc]), &Bt[(long long)(bn + lr + p * 32) * DHID + k0 + lc]);
        }
        cp_commit();
    };

    float acc[4][4][4];
    #pragma unroll
    for (int i = 0; i < 4; i++)
        #pragma unroll
        for (int j = 0; j < 4; j++)
            #pragma unroll
            for (int e = 0; e < 4; e++) acc[i][j][e] = 0.0f;

    issue(0, 0);
    issue(32, 1);

    for (int it = 0; it < 32; it++) {
        if (it == 31) cp_wait0(); else cp_wait1();   // tail-aware drain
        __syncthreads();
        if (it + 2 < 32) issue((it + 2) * 32, (it + 2) % 3);

        const uint32_t* as = reinterpret_cast<const uint32_t*>(smem + (it % 3) * 2 * GSTG);
        const uint32_t* bs = as + GSTG;

        #pragma unroll
        for (int ks = 0; ks < 4; ks++) {
            const int kk = ks * 8;
            uint32_t af[4][4], bf[4][2];
            #pragma unroll
            for (int mf = 0; mf < 4; mf++) {
                const int r = wm + mf * 16 + gid;
                af[mf][0] = as[r       * 36 + kk + ctid];
                af[mf][1] = as[(r + 8) * 36 + kk + ctid];
                af[mf][2] = as[r       * 36 + kk + ctid + 4];
                af[mf][3] = as[(r + 8) * 36 + kk + ctid + 4];
            }
            #pragma unroll
            for (int nf = 0; nf < 4; nf++) {
                const int c = wn + nf * 8 + gid;
                bf[nf][0] = bs[c * 36 + kk + ctid];
                bf[nf][1] = bs[c * 36 + kk + ctid + 4];
            }
            #pragma unroll
            for (int mf = 0; mf < 4; mf++)
                #pragma unroll
                for (int nf = 0; nf < 4; nf++)
                    mma_tf32(acc[mf][nf], af[mf], bf[nf]);
        }
    }

    const bool rnd = (jb.mode != MODE_PLAIN);
    #pragma unroll
    for (int mf = 0; mf < 4; mf++) {
        #pragma unroll
        for (int nf = 0; nf < 4; nf++) {
            const int r0 = bm + wm + mf * 16 + gid;
            const int c0 = bn + wn + nf * 8 + 2 * ctid;
            const float b0 = jb.bias ? jb.bias[c0]     : 0.0f;
            const float b1 = jb.bias ? jb.bias[c0 + 1] : 0.0f;
            float v00 = (acc[mf][nf][0] + b0) * jb.alpha;
            float v01 = (acc[mf][nf][1] + b1) * jb.alpha;
            float v10 = (acc[mf][nf][2] + b0) * jb.alpha;
            float v11 = (acc[mf][nf][3] + b1) * jb.alpha;
            if (rnd) {
                v00 = __uint_as_float(f2tf(v00)); v01 = __uint_as_float(f2tf(v01));
                v10 = __uint_as_float(f2tf(v10)); v11 = __uint_as_float(f2tf(v11));
            }
            long long i0, i1;
            if (jb.mode == MODE_PLAIN) {
                i0 = (long long)r0 * DHID + c0;
                i1 = (long long)(r0 + 8) * DHID + c0;
            } else {
                const int h  = c0 >> 6, hd = c0 & 63;
                const int b_  = r0 / jb.S, s0 = r0 - b_ * jb.S;
                const int b_2 = (r0 + 8) / jb.S, s1 = (r0 + 8) - b_2 * jb.S;
                if (jb.mode == MODE_QSPLIT) {
                    i0 = (((long long)(b_  * NHEAD + h)) * jb.S + s0) * HDIM + hd;
                    i1 = (((long long)(b_2 * NHEAD + h)) * jb.S + s1) * HDIM + hd;
                } else {
                    i0 = (((long long)(b_  * NHEAD + h)) * SKV + jb.off + s0) * HDIM + hd;
                    i1 = (((long long)(b_2 * NHEAD + h)) * SKV + jb.off + s1) * HDIM + hd;
                }
            }
            *reinterpret_cast<float2*>(&jb.C[i0]) = make_float2(v00, v01);
            *reinterpret_cast<float2*>(&jb.C[i1]) = make_float2(v10, v11);
        }
    }
}

// ---------------- scores kernel: Q·Kᵀ + softmax + w write, scores in REGISTERS ----
// 512 threads, 32 q-rows per block. Score fragments in sacc[9][2][4] = 72 regs.
// NO min-blocks clause: ptxas gets 128 regs/thread (1 CTA/SM) -> no spills.
// Q fragments are re-read from smem per k-step (cheap) instead of hoisted (-64 regs).
#define SCHUNK 128
#define SNCH 9                      // ceil(1088/128); last chunk = 64 cols
#define SCORES_SMEM ((32 * Q_STRIDE + 2 * SCHUNK * KV_STRIDE + 32 * 16 + 32) * 4)

__global__ __launch_bounds__(512) void scores_kernel(
    const float* __restrict__ Qt, const float* __restrict__ Qi,
    const float* __restrict__ Kg,
    float* __restrict__ Wt, float* __restrict__ Wi)
{
    extern __shared__ float smf[];
    float* Qs      = smf;                                  // 32 x Q_STRIDE
    float* KV      = Qs + 32 * Q_STRIDE;                   // 2 x SCHUNK x KV_STRIDE
    float* red     = KV + 2 * SCHUNK * KV_STRIDE;          // 32 x 16
    float* rowstat = red + 32 * 16;                        // 32

    const bool isT = blockIdx.x < (ST / 32);
    const int  Sq  = isT ? ST : SI;
    const float* Q   = isT ? Qt : Qi;
    float* Wout      = isT ? Wt : Wi;
    const int qbase  = (isT ? blockIdx.x : blockIdx.x - ST / 32) * 32;

    const int z = blockIdx.y;
    const int tid  = threadIdx.x;
    const int w    = tid >> 5;          // 0..15
    const int lane = tid & 31;
    const int gid  = lane >> 2;
    const int ctid = lane & 3;

    auto issueK = [&](int c, int s) {
        float* dst = KV + s * SCHUNK * KV_STRIDE;
        const int rows = (c == SNCH - 1) ? (SKV - c * SCHUNK) : SCHUNK;
        for (int i = tid; i < rows * 16; i += 512) {
            const int r = i >> 4, c4 = (i & 15) * 4;
            cp16(s2u(&dst[r * KV_STRIDE + c4]), &Kg[((long long)z * SKV + c * SCHUNK + r) * HDIM + c4]);
        }
        cp_commit();
    };

    // group 0: Q + K chunk 0
    for (int i = tid; i < 32 * 16; i += 512) {
        const int r = i >> 4, c4 = (i & 15) * 4;
        cp16(s2u(&Qs[r * Q_STRIDE + c4]), &Q[((long long)z * Sq + qbase + r) * HDIM + c4]);
    }
    issueK(0, 0);
    cp_wait0();
    __syncthreads();

    const uint32_t* Qsu = reinterpret_cast<const uint32_t*>(Qs);

    // ---- phase 1: scores into registers ----
    // thread covers rows {gid, gid+8, gid+16, gid+24}, cols {c*128 + w*8 + 2ctid, +1}
    float sacc[SNCH][2][4];
    #pragma unroll
    for (int c = 0; c < SNCH; c++) {
        if (c > 0) { cp_wait0(); __syncthreads(); }
        if (c + 1 < SNCH) issueK(c + 1, (c + 1) & 1);

        const int cw = (c == SNCH - 1) ? (SKV - c * SCHUNK) : SCHUNK;
        const uint32_t* buf = reinterpret_cast<const uint32_t*>(KV + (c & 1) * SCHUNK * KV_STRIDE);
        if (w * 8 < cw) {
            #pragma unroll
            for (int mf = 0; mf < 2; mf++)
                #pragma unroll
                for (int e = 0; e < 4; e++) sacc[c][mf][e] = 0.0f;

            const int col = w * 8 + gid;
            #pragma unroll
            for (int ks = 0; ks < 8; ks++) {
                const int kk = ks * 8;
                uint32_t bf[2], af[2][4];
                bf[0] = buf[col * KV_STRIDE + kk + ctid];
                bf[1] = buf[col * KV_STRIDE + kk + ctid + 4];
                #pragma unroll
                for (int mf = 0; mf < 2; mf++) {
                    const int r = mf * 16 + gid;
                    af[mf][0] = Qsu[r       * Q_STRIDE + kk + ctid];
                    af[mf][1] = Qsu[(r + 8) * Q_STRIDE + kk + ctid];
                    af[mf][2] = Qsu[r       * Q_STRIDE + kk + ctid + 4];
                    af[mf][3] = Qsu[(r + 8) * Q_STRIDE + kk + ctid + 4];
                }
                mma_tf32(sacc[c][0], af[0], bf);
                mma_tf32(sacc[c][1], af[1], bf);
            }
        }
    }
    const bool tailAct = (w < 8);   // warps 8..15 have no chunk-8 columns

    // ---- row max ----
    float pm[4] = {-1e30f, -1e30f, -1e30f, -1e30f};
    #pragma unroll
    for (int c = 0; c < SNCH - 1; c++) {
        pm[0] = fmaxf(pm[0], fmaxf(sacc[c][0][0], sacc[c][0][1]));
        pm[1] = fmaxf(pm[1], fmaxf(sacc[c][0][2], sacc[c][0][3]));
        pm[2] = fmaxf(pm[2], fmaxf(sacc[c][1][0], sacc[c][1][1]));
        pm[3] = fmaxf(pm[3], fmaxf(sacc[c][1][2], sacc[c][1][3]));
    }
    if (tailAct) {
        pm[0] = fmaxf(pm[0], fmaxf(sacc[SNCH-1][0][0], sacc[SNCH-1][0][1]));
        pm[1] = fmaxf(pm[1], fmaxf(sacc[SNCH-1][0][2], sacc[SNCH-1][0][3]));
        pm[2] = fmaxf(pm[2], fmaxf(sacc[SNCH-1][1][0], sacc[SNCH-1][1][1]));
        pm[3] = fmaxf(pm[3], fmaxf(sacc[SNCH-1][1][2], sacc[SNCH-1][1][3]));
    }
    #pragma unroll
    for (int j = 0; j < 4; j++) {
        pm[j] = fmaxf(pm[j], __shfl_xor_sync(0xffffffffu, pm[j], 1));
        pm[j] = fmaxf(pm[j], __shfl_xor_sync(0xffffffffu, pm[j], 2));
    }
    if (ctid == 0) {
        red[gid        * 16 + w] = pm[0];
        red[(gid + 8)  * 16 + w] = pm[1];
        red[(gid + 16) * 16 + w] = pm[2];
        red[(gid + 24) * 16 + w] = pm[3];
    }
    __syncthreads();
    if (tid < 32) {
        float m = red[tid * 16];
        #pragma unroll
        for (int i = 1; i < 16; i++) m = fmaxf(m, red[tid * 16 + i]);
        rowstat[tid] = m;
    }
    __syncthreads();
    const float m0 = rowstat[gid], m1 = rowstat[gid + 8];
    const float m2 = rowstat[gid + 16], m3 = rowstat[gid + 24];

    // ---- exp in regs + row sum ----
    float ps[4] = {0.0f, 0.0f, 0.0f, 0.0f};
    #pragma unroll
    for (int c = 0; c < SNCH - 1; c++) {
        sacc[c][0][0] = __expf(sacc[c][0][0] - m0); ps[0] += sacc[c][0][0];
        sacc[c][0][1] = __expf(sacc[c][0][1] - m0); ps[0] += sacc[c][0][1];
        sacc[c][0][2] = __expf(sacc[c][0][2] - m1); ps[1] += sacc[c][0][2];
        sacc[c][0][3] = __expf(sacc[c][0][3] - m1); ps[1] += sacc[c][0][3];
        sacc[c][1][0] = __expf(sacc[c][1][0] - m2); ps[2] += sacc[c][1][0];
        sacc[c][1][1] = __expf(sacc[c][1][1] - m2); ps[2] += sacc[c][1][1];
        sacc[c][1][2] = __expf(sacc[c][1][2] - m3); ps[3] += sacc[c][1][2];
        sacc[c][1][3] = __expf(sacc[c][1][3] - m3); ps[3] += sacc[c][1][3];
    }
    if (tailAct) {
        const int c = SNCH - 1;
        sacc[c][0][0] = __expf(sacc[c][0][0] - m0); ps[0] += sacc[c][0][0];
        sacc[c][0][1] = __expf(sacc[c][0][1] - m0); ps[0] += sacc[c][0][1];
        sacc[c][0][2] = __expf(sacc[c][0][2] - m1); ps[1] += sacc[c][0][2];
        sacc[c][0][3] = __expf(sacc[c][0][3] - m1); ps[1] += sacc[c][0][3];
        sacc[c][1][0] = __expf(sacc[c][1][0] - m2); ps[2] += sacc[c][1][0];
        sacc[c][1][1] = __expf(sacc[c][1][1] - m2); ps[2] += sacc[c][1][1];
        sacc[c][1][2] = __expf(sacc[c][1][2] - m3); ps[3] += sacc[c][1][2];
        sacc[c][1][3] = __expf(sacc[c][1][3] - m3); ps[3] += sacc[c][1][3];
    }
    #pragma unroll
    for (int j = 0; j < 4; j++) {
        ps[j] += __shfl_xor_sync(0xffffffffu, ps[j], 1);
        ps[j] += __shfl_xor_sync(0xffffffffu, ps[j], 2);
    }
    __syncthreads();   // rowstat reads done before red is overwritten
    if (ctid == 0) {
        red[gid        * 16 + w] = ps[0];
        red[(gid + 8)  * 16 + w] = ps[1];
        red[(gid + 16) * 16 + w] = ps[2];
        red[(gid + 24) * 16 + w] = ps[3];
    }
    __syncthreads();
    if (tid < 32) {
        float s = red[tid * 16];
        #pragma unroll
        for (int i = 1; i < 16; i++) s += red[tid * 16 + i];
        rowstat[tid] = 1.0f / s;
    }
    __syncthreads();
    const float i0 = rowstat[gid], i1 = rowstat[gid + 8];
    const float i2 = rowstat[gid + 16], i3 = rowstat[gid + 24];

    // ---- w write from registers (streaming stores; 4x8B per 32B sector) ----
    float* base = Wout + ((long long)z * Sq + qbase) * SKV;
    #pragma unroll
    for (int c = 0; c < SNCH - 1; c++) {
        const int c0 = c * SCHUNK + w * 8 + 2 * ctid;
        stg_cs2(base + (gid)        * SKV + c0, sacc[c][0][0] * i0, sacc[c][0][1] * i0);
        stg_cs2(base + (gid + 8)  * SKV + c0, sacc[c][0][2] * i1, sacc[c][0][3] * i1);
        stg_cs2(base + (gid + 16) * SKV + c0, sacc[c][1][0] * i2, sacc[c][1][1] * i2);
        stg_cs2(base + (gid + 24) * SKV + c0, sacc[c][1][2] * i3, sacc[c][1][3] * i3);
    }
    if (tailAct) {
        const int c = SNCH - 1;
        const int c0 = c * SCHUNK + w * 8 + 2 * ctid;
        stg_cs2(base + (gid)        * SKV + c0, sacc[c][0][0] * i0, sacc[c][0][1] * i0);
        stg_cs2(base + (gid + 8)  * SKV + c0, sacc[c][0][2] * i1, sacc[c][0][3] * i1);
        stg_cs2(base + (gid + 16) * SKV + c0, sacc[c][1][0] * i2, sacc[c][1][1] * i2);
        stg_cs2(base + (gid + 24) * SKV + c0, sacc[c][1][2] * i3, sacc[c][1][3] * i3);
    }
}

// ---------------- AV kernel: O = w · V (batched 128x64x1088 tf32 GEMM) ----------------
#define AV_ASTG (128 * 36)
#define AV_BSTG (32 * KV_STRIDE)
#define AV_STG  (AV_ASTG + AV_BSTG)
#define AV_SMEM (3 * AV_STG * 4)      // 82944 bytes
#define AV_NKIT (SKV / 32)            // 34

__global__ __launch_bounds__(256, 2) void av_kernel(
    const float* __restrict__ Wt, const float* __restrict__ Wi,
    const float* __restrict__ Vg,
    float* __restrict__ Ot, float* __restrict__ Oi)
{
    extern __shared__ float smem[];
    const int mt = blockIdx.y;           // 0..3 text, 4..8 image
    const bool isT = mt < 4;
    const int Sq = isT ? ST : SI;
    const float* Wsrc = isT ? Wt : Wi;
    float* O = isT ? Ot : Oi;
    const int bm = (isT ? mt : mt - 4) * 128;
    const int z = blockIdx.z;
    const int b = z >> 4, h = z & 15;
    const float* A = Wsrc + (long long)z * Sq * SKV;
    const float* V = Vg + (long long)z * SKV * HDIM;

    const int tid  = threadIdx.x;
    const int w    = tid >> 5;
    const int lane = tid & 31;
    const int gid  = lane >> 2;
    const int ctid = lane & 3;
    const int wm = (w & 1) * 64;
    const int wn = (w >> 1) * 16;

    const int lrA = tid >> 3, lcA = (tid & 7) * 4;
    const int lrB = tid >> 4, lcB = (tid & 15) * 4;

    auto issue = [&](int k0, int s) {
        float* as = smem + s * AV_STG;
        float* bs = as + AV_ASTG;
        #pragma unroll
        for (int p = 0; p < 4; p++) {
            int ar = bm + lrA + p * 32;
            if (ar >= Sq) ar = Sq - 1;          // clamp (dup rows; stores guarded)
            cp16(s2u(&as[(lrA + p * 32) * 36 + lcA]), &A[(long long)ar * SKV + k0 + lcA]);
        }
        #pragma unroll
        for (int p = 0; p < 2; p++) {
            cp16(s2u(&bs[(lrB + p * 16) * KV_STRIDE + lcB]), &V[(long long)(k0 + lrB + p * 16) * HDIM + lcB]);
        }
        cp_commit();
    };

    float acc[4][2][4];
    #pragma unroll
    for (int i = 0; i < 4; i++)
        #pragma unroll
        for (int j = 0; j < 2; j++)
            #pragma unroll
            for (int e = 0; e < 4; e++) acc[i][j][e] = 0.0f;

    issue(0, 0);
    issue(32, 1);

    for (int it = 0; it < AV_NKIT; it++) {
        if (it == AV_NKIT - 1) cp_wait0(); else cp_wait1();
        __syncthreads();
        if (it + 2 < AV_NKIT) issue((it + 2) * 32, (it + 2) % 3);

        const float*    as = smem + (it % 3) * AV_STG;
        const uint32_t* bs = reinterpret_cast<const uint32_t*>(as + AV_ASTG);

        #pragma unroll
        for (int ks = 0; ks < 4; ks++) {
            const int kk = ks * 8;
            uint32_t af[4][4], bf[2][2];
            #pragma unroll
            for (int mf = 0; mf < 4; mf++) {
                const int r = wm + mf * 16 + gid;
                af[mf][0] = f2tf(as[r       * 36 + kk + ctid]);
                af[mf][1] = f2tf(as[(r + 8) * 36 + kk + ctid]);
                af[mf][2] = f2tf(as[r       * 36 + kk + ctid + 4]);
                af[mf][3] = f2tf(as[(r + 8) * 36 + kk + ctid + 4]);
            }
            #pragma unroll
            for (int nf = 0; nf < 2; nf++) {
                const int col = wn + nf * 8 + gid;
                bf[nf][0] = bs[(kk + ctid)     * KV_STRIDE + col];
                bf[nf][1] = bs[(kk + ctid + 4) * KV_STRIDE + col];
            }
            #pragma unroll
            for (int mf = 0; mf < 4; mf++)
                #pragma unroll
                for (int nf = 0; nf < 2; nf++)
                    mma_tf32(acc[mf][nf], af[mf], bf[nf]);
        }
    }

    #pragma unroll
    for (int mf = 0; mf < 4; mf++) {
        #pragma unroll
        for (int nf = 0; nf < 2; nf++) {
            const int r0 = bm + wm + mf * 16 + gid;
            const int c0 = h * HDIM + wn + nf * 8 + 2 * ctid;
            if (r0 < Sq) {
                float2 v = make_float2(__uint_as_float(f2tf(acc[mf][nf][0])),
                                       __uint_as_float(f2tf(acc[mf][nf][1])));
                *reinterpret_cast<float2*>(&O[((long long)b * Sq + r0) * DHID + c0]) = v;
            }
            if (r0 + 8 < Sq) {
                float2 v = make_float2(__uint_as_float(f2tf(acc[mf][nf][2])),
                                       __uint_as_float(f2tf(acc[mf][nf][3])));
                *reinterpret_cast<float2*>(&O[((long long)b * Sq + r0 + 8) * DHID + c0]) = v;
            }
        }
    }
}

// ---------------- host orchestration ----------------
extern "C" void kernel_launch(void* const* d_in, const int* in_sizes, int n_in,
                              void* d_out, int out_size)
{
    const float* q_text  = (const float*)d_in[0];
    const float* q_image = (const float*)d_in[1];
    const float* k_text  = (const float*)d_in[2];
    const float* k_image = (const float*)d_in[3];
    const float* Wq_t = (const float*)d_in[4];  const float* bq_t = (const float*)d_in[5];
    const float* Wk_t = (const float*)d_in[6];  const float* bk_t = (const float*)d_in[7];
    const float* Wv_t = (const float*)d_in[8];  const float* bv_t = (const float*)d_in[9];
    const float* Wq_i = (const float*)d_in[10]; const float* bq_i = (const float*)d_in[11];
    const float* Wk_i = (const float*)d_in[12]; const float* bk_i = (const float*)d_in[13];
    const float* Wv_i = (const float*)d_in[14]; const float* bv_i = (const float*)d_in[15];
    const float* lng_t = (const float*)d_in[16]; const float* lnb_t = (const float*)d_in[17];
    const float* lng_i = (const float*)d_in[18]; const float* lnb_i = (const float*)d_in[19];
    const float* Wo = (const float*)d_in[20]; const float* bo = (const float*)d_in[21];

    float* out = (float*)d_out;
    const long long OUT_T = 0;
    const long long OUT_I = (long long)BATCH * ST * DHID;
    const long long W_T   = OUT_I + (long long)BATCH * SI * DHID;
    const long long W_I   = W_T + (long long)BATCH * NHEAD * ST * SKV;

    float *pLNQT, *pLNQI, *pLNKT, *pLNKI, *pQT, *pQI, *pK, *pV, *pOT, *pOI, *pWc;
    cudaGetSymbolAddress((void**)&pLNQT, g_ln_qt);
    cudaGetSymbolAddress((void**)&pLNQI, g_ln_qi);
    cudaGetSymbolAddress((void**)&pLNKT, g_ln_kt);
    cudaGetSymbolAddress((void**)&pLNKI, g_ln_ki);
    cudaGetSymbolAddress((void**)&pQT,   g_Q_t);
    cudaGetSymbolAddress((void**)&pQI,   g_Q_i);
    cudaGetSymbolAddress((void**)&pK,    g_K);
    cudaGetSymbolAddress((void**)&pV,    g_V);
    cudaGetSymbolAddress((void**)&pOT,   g_O_t);
    cudaGetSymbolAddress((void**)&pOI,   g_O_i);
    cudaGetSymbolAddress((void**)&pWc,   g_Wc);

    const long long WSZ = (long long)DHID * DHID;
    float* cWq_t = pWc + 0 * WSZ;  float* cWk_t = pWc + 1 * WSZ;  float* cWv_t = pWc + 2 * WSZ;
    float* cWq_i = pWc + 3 * WSZ;  float* cWk_i = pWc + 4 * WSZ;  float* cWv_i = pWc + 5 * WSZ;
    float* cWo   = pWc + 6 * WSZ;

    cudaFuncSetAttribute(gemm_tf32_multi, cudaFuncAttributeMaxDynamicSharedMemorySize, GEMM_SMEM);
    cudaFuncSetAttribute(scores_kernel,   cudaFuncAttributeMaxDynamicSharedMemorySize, SCORES_SMEM);
    cudaFuncSetAttribute(av_kernel,       cudaFuncAttributeMaxDynamicSharedMemorySize, AV_SMEM);

    // 0) weight pre-round (7 jobs)
    {
        CvtBatch cb;
        cb.j[0] = { Wq_t, cWq_t }; cb.j[1] = { Wk_t, cWk_t }; cb.j[2] = { Wv_t, cWv_t };
        cb.j[3] = { Wq_i, cWq_i }; cb.j[4] = { Wk_i, cWk_i }; cb.j[5] = { Wv_i, cWv_i };
        cb.j[6] = { Wo, cWo };
        cvt_multi<<<dim3(DHID * DHID / (256 * 4), 7), 256>>>(cb);
    }

    // 1) LayerNorms (outputs pre-rounded tf32)
    {
        LnBatch lb;
        lb.j[0] = { q_text,  lng_t, lnb_t, pLNQT, BATCH * ST };
        lb.j[1] = { q_image, lng_i, lnb_i, pLNQI, BATCH * SI };
        lb.j[2] = { k_text,  lng_t, lnb_t, pLNKT, BATCH * ST };
        lb.j[3] = { k_image, lng_i, lnb_i, pLNKI, BATCH * SI };
        ln_multi<<<dim3(BATCH * SI, 4), 256>>>(lb);
    }

    // 2) Projections (one launch, 6 jobs)
    {
        GemmBatch gb;
        gb.j[0] = { pLNQT, cWq_t, pQT, bq_t, BATCH * ST, MODE_QSPLIT, ST, 0,  QSCALE };
        gb.j[1] = { pLNQI, cWq_i, pQI, bq_i, BATCH * SI, MODE_QSPLIT, SI, 0,  QSCALE };
        gb.j[2] = { pLNKT, cWk_t, pK,  bk_t, BATCH * ST, MODE_KV,     ST, 0,  1.0f };
        gb.j[3] = { pLNKI, cWk_i, pK,  bk_i, BATCH * SI, MODE_KV,     SI, ST, 1.0f };
        gb.j[4] = { pLNKT, cWv_t, pV,  bv_t, BATCH * ST, MODE_KV,     ST, 0,  1.0f };
        gb.j[5] = { pLNKI, cWv_i, pV,  bv_i, BATCH * SI, MODE_KV,     SI, ST, 1.0f };
        gemm_tf32_multi<<<dim3(DHID / 128, (BATCH * SI) / 128, 6), 256, GEMM_SMEM>>>(gb);
    }

    // 3) Scores + softmax + w (register-resident scores, no spills)
    scores_kernel<<<dim3(ST / 32 + SI / 32, BATCH * NHEAD), 512, SCORES_SMEM>>>(
        pQT, pQI, pK, out + W_T, out + W_I);

    // 4) O = w · V (batched GEMM, 2 CTAs/SM)
    av_kernel<<<dim3(1, 9, BATCH * NHEAD), 256, AV_SMEM>>>(
        out + W_T, out + W_I, pV, pOT, pOI);

    // 5) Output projection (one launch, 2 jobs)
    {
        GemmBatch gb;
        gb.j[0] = { pOT, cWo, out + OUT_T, bo, BATCH * ST, MODE_PLAIN, 0, 0, 1.0f };
        gb.j[1] = { pOI, cWo, out + OUT_I, bo, BATCH * SI, MODE_PLAIN, 0, 0, 1.0f };
        gb.j[2] = gb.j[1]; gb.j[3] = gb.j[1]; gb.j[4] = gb.j[1]; gb.j[5] = gb.j[1];
        gemm_tf32_multi<<<dim3(DHID / 128, (BATCH * SI) / 128, 2), 256, GEMM_SMEM>>>(gb);
    }

    (void)in_sizes; (void)n_in; (void)out_size;
}

// round 17
// speedup vs baseline: 1.2362x; 1.0572x over previous
#include <cuda_runtime.h>
#include <cstdint>

#define DHID  1024
#define NHEAD 16
#define HDIM  64
#define BATCH 4
#define ST    512
#define SI    576
#define SKV   1088
#define QSCALE 0.125f
#define LN_EPS 1e-5f

#define Q_STRIDE  68     // Q staging stride, %32==4
#define KV_STRIDE 72     // K/V chunk stride, %32==8

// ---------------- scratch (device globals; allocation-free) ----------------
__device__ float g_ln_qt[BATCH * ST * DHID];
__device__ float g_ln_qi[BATCH * SI * DHID];
__device__ float g_ln_kt[BATCH * ST * DHID];
__device__ float g_ln_ki[BATCH * SI * DHID];
__device__ float g_Q_t[BATCH * NHEAD * ST * HDIM];
__device__ float g_Q_i[BATCH * NHEAD * SI * HDIM];
__device__ float g_K  [BATCH * NHEAD * SKV * HDIM];
__device__ float g_V  [BATCH * NHEAD * SKV * HDIM];
__device__ float g_O_t[BATCH * ST * DHID];
__device__ float g_O_i[BATCH * SI * DHID];
__device__ float g_Wc [7 * DHID * DHID];   // pre-rounded tf32 weights

// ---------------- helpers ----------------
__device__ __forceinline__ uint32_t f2tf(float f) {
    uint32_t u; asm("cvt.rna.tf32.f32 %0, %1;" : "=r"(u) : "f"(f)); return u;
}
__device__ __forceinline__ void mma_tf32(float* d, const uint32_t* a, const uint32_t* b) {
    asm volatile("mma.sync.aligned.m16n8k8.row.col.f32.tf32.tf32.f32 "
                 "{%0,%1,%2,%3}, {%4,%5,%6,%7}, {%8,%9}, {%0,%1,%2,%3};"
                 : "+f"(d[0]), "+f"(d[1]), "+f"(d[2]), "+f"(d[3])
                 : "r"(a[0]), "r"(a[1]), "r"(a[2]), "r"(a[3]), "r"(b[0]), "r"(b[1]));
}
__device__ __forceinline__ uint32_t s2u(const void* p) {
    return (uint32_t)__cvta_generic_to_shared(p);
}
__device__ __forceinline__ void cp16(uint32_t dst, const void* src) {
    asm volatile("cp.async.cg.shared.global [%0], [%1], 16;" :: "r"(dst), "l"(src));
}
__device__ __forceinline__ void cp_commit() {
    asm volatile("cp.async.commit_group;");
}
__device__ __forceinline__ void cp_wait0() {
    asm volatile("cp.async.wait_group 0;" ::: "memory");
}
__device__ __forceinline__ void cp_wait1() {
    asm volatile("cp.async.wait_group 1;" ::: "memory");
}
__device__ __forceinline__ void stg_cs2(float* p, float x, float y) {
    asm volatile("st.global.cs.v2.f32 [%0], {%1, %2};" :: "l"(p), "f"(x), "f"(y));
}

// ---------------- tf32 pre-round for weights (7 jobs, one launch) ----------------
struct CvtJob { const float* in; float* out; };
struct CvtBatch { CvtJob j[7]; };

__global__ __launch_bounds__(256) void cvt_multi(CvtBatch batch)
{
    const CvtJob jb = batch.j[blockIdx.y];
    const int i = blockIdx.x * 256 + threadIdx.x;
    float4 v = reinterpret_cast<const float4*>(jb.in)[i];
    uint4 u = make_uint4(f2tf(v.x), f2tf(v.y), f2tf(v.z), f2tf(v.w));
    reinterpret_cast<uint4*>(jb.out)[i] = u;
}

// ---------------- LayerNorm (4 jobs; output pre-rounded tf32) ----------------
struct LnJob { const float* x; const float* g; const float* b; float* y; int rows; };
struct LnBatch { LnJob j[4]; };

__global__ __launch_bounds__(256) void ln_multi(LnBatch batch)
{
    const LnJob jb = batch.j[blockIdx.y];
    const int row = blockIdx.x;
    if (row >= jb.rows) return;
    const int t = threadIdx.x;
    const float4 xv = reinterpret_cast<const float4*>(jb.x + (long long)row * DHID)[t];

    float s  = xv.x + xv.y + xv.z + xv.w;
    float sq = xv.x * xv.x + xv.y * xv.y + xv.z * xv.z + xv.w * xv.w;

    __shared__ float red_s[8], red_q[8];
    #pragma unroll
    for (int o = 16; o > 0; o >>= 1) {
        s  += __shfl_xor_sync(0xffffffffu, s,  o);
        sq += __shfl_xor_sync(0xffffffffu, sq, o);
    }
    if ((t & 31) == 0) { red_s[t >> 5] = s; red_q[t >> 5] = sq; }
    __syncthreads();
    float ts = red_s[t & 7], tq = red_q[t & 7];
    #pragma unroll
    for (int o = 4; o > 0; o >>= 1) {
        ts += __shfl_xor_sync(0xffffffffu, ts, o);
        tq += __shfl_xor_sync(0xffffffffu, tq, o);
    }
    ts = __shfl_sync(0xffffffffu, ts, 0);
    tq = __shfl_sync(0xffffffffu, tq, 0);

    const float mean = ts * (1.0f / DHID);
    const float rstd = rsqrtf(tq * (1.0f / DHID) - mean * mean + LN_EPS);

    const float4 gv = reinterpret_cast<const float4*>(jb.g)[t];
    const float4 bv = reinterpret_cast<const float4*>(jb.b)[t];
    uint4 o;
    o.x = f2tf((xv.x - mean) * rstd * gv.x + bv.x);
    o.y = f2tf((xv.y - mean) * rstd * gv.y + bv.y);
    o.z = f2tf((xv.z - mean) * rstd * gv.z + bv.z);
    o.w = f2tf((xv.w - mean) * rstd * gv.w + bv.w);
    reinterpret_cast<uint4*>(jb.y + (long long)row * DHID)[t] = o;
}

// ---------------- batched tf32 GEMM (3-stage cp.async; no inner cvt) ----------------
#define MODE_PLAIN  0   // fp32 store (final outputs)
#define MODE_QSPLIT 1   // tf32-rounded store
#define MODE_KV     2   // tf32-rounded store

struct GemmJob {
    const float* A; const float* Bt; float* C; const float* bias;
    int M; int mode; int S; int off; float alpha;
};
struct GemmBatch { GemmJob j[6]; };

#define GSTG (128 * 36)
#define GEMM_SMEM (6 * GSTG * 4)   // 3 stages x (A+B) = 110592 bytes

__global__ __launch_bounds__(256, 2) void gemm_tf32_multi(GemmBatch batch)
{
    extern __shared__ float smem[];
    const GemmJob jb = batch.j[blockIdx.z];
    const int bm = blockIdx.y * 128;
    if (bm >= jb.M) return;
    const int bn = blockIdx.x * 128;

    const int tid  = threadIdx.x;
    const int w    = tid >> 5;
    const int lane = tid & 31;
    const int gid  = lane >> 2;
    const int ctid = lane & 3;
    const int wm = (w & 1) * 64;
    const int wn = (w >> 1) * 32;
    const int lr = tid >> 3;
    const int lc = (tid & 7) * 4;

    const float* A  = jb.A;
    const float* Bt = jb.Bt;

    auto issue = [&](int k0, int s) {
        float* as = smem + s * 2 * GSTG;
        float* bs = as + GSTG;
        #pragma unroll
        for (int p = 0; p < 4; p++) {
            cp16(s2u(&as[(lr + p * 32) * 36 + lc]), &A [(long long)(bm + lr + p * 32) * DHID + k0 + lc]);
            cp16(s2u(&bs[(lr + p * 32) * 36 + lc]), &Bt[(long long)(bn + lr + p * 32) * DHID + k0 + lc]);
        }
        cp_commit();
    };

    float acc[4][4][4];
    #pragma unroll
    for (int i = 0; i < 4; i++)
        #pragma unroll
        for (int j = 0; j < 4; j++)
            #pragma unroll
            for (int e = 0; e < 4; e++) acc[i][j][e] = 0.0f;

    issue(0, 0);
    issue(32, 1);

    for (int it = 0; it < 32; it++) {
        if (it == 31) cp_wait0(); else cp_wait1();   // tail-aware drain
        __syncthreads();
        if (it + 2 < 32) issue((it + 2) * 32, (it + 2) % 3);

        const uint32_t* as = reinterpret_cast<const uint32_t*>(smem + (it % 3) * 2 * GSTG);
        const uint32_t* bs = as + GSTG;

        #pragma unroll
        for (int ks = 0; ks < 4; ks++) {
            const int kk = ks * 8;
            uint32_t af[4][4], bf[4][2];
            #pragma unroll
            for (int mf = 0; mf < 4; mf++) {
                const int r = wm + mf * 16 + gid;
                af[mf][0] = as[r       * 36 + kk + ctid];
                af[mf][1] = as[(r + 8) * 36 + kk + ctid];
                af[mf][2] = as[r       * 36 + kk + ctid + 4];
                af[mf][3] = as[(r + 8) * 36 + kk + ctid + 4];
            }
            #pragma unroll
            for (int nf = 0; nf < 4; nf++) {
                const int c = wn + nf * 8 + gid;
                bf[nf][0] = bs[c * 36 + kk + ctid];
                bf[nf][1] = bs[c * 36 + kk + ctid + 4];
            }
            #pragma unroll
            for (int mf = 0; mf < 4; mf++)
                #pragma unroll
                for (int nf = 0; nf < 4; nf++)
                    mma_tf32(acc[mf][nf], af[mf], bf[nf]);
        }
    }

    const bool rnd = (jb.mode != MODE_PLAIN);
    #pragma unroll
    for (int mf = 0; mf < 4; mf++) {
        #pragma unroll
        for (int nf = 0; nf < 4; nf++) {
            const int r0 = bm + wm + mf * 16 + gid;
            const int c0 = bn + wn + nf * 8 + 2 * ctid;
            const float b0 = jb.bias ? jb.bias[c0]     : 0.0f;
            const float b1 = jb.bias ? jb.bias[c0 + 1] : 0.0f;
            float v00 = (acc[mf][nf][0] + b0) * jb.alpha;
            float v01 = (acc[mf][nf][1] + b1) * jb.alpha;
            float v10 = (acc[mf][nf][2] + b0) * jb.alpha;
            float v11 = (acc[mf][nf][3] + b1) * jb.alpha;
            if (rnd) {
                v00 = __uint_as_float(f2tf(v00)); v01 = __uint_as_float(f2tf(v01));
                v10 = __uint_as_float(f2tf(v10)); v11 = __uint_as_float(f2tf(v11));
            }
            long long i0, i1;
            if (jb.mode == MODE_PLAIN) {
                i0 = (long long)r0 * DHID + c0;
                i1 = (long long)(r0 + 8) * DHID + c0;
            } else {
                const int h  = c0 >> 6, hd = c0 & 63;
                const int b_  = r0 / jb.S, s0 = r0 - b_ * jb.S;
                const int b_2 = (r0 + 8) / jb.S, s1 = (r0 + 8) - b_2 * jb.S;
                if (jb.mode == MODE_QSPLIT) {
                    i0 = (((long long)(b_  * NHEAD + h)) * jb.S + s0) * HDIM + hd;
                    i1 = (((long long)(b_2 * NHEAD + h)) * jb.S + s1) * HDIM + hd;
                } else {
                    i0 = (((long long)(b_  * NHEAD + h)) * SKV + jb.off + s0) * HDIM + hd;
                    i1 = (((long long)(b_2 * NHEAD + h)) * SKV + jb.off + s1) * HDIM + hd;
                }
            }
            *reinterpret_cast<float2*>(&jb.C[i0]) = make_float2(v00, v01);
            *reinterpret_cast<float2*>(&jb.C[i1]) = make_float2(v10, v11);
        }
    }
}

// ---------------- scores kernel: Q·Kᵀ + softmax + w write, scores in REGISTERS ----
// 512 threads, 32 q-rows per block. Score fragments in sacc[9][2][4] = 72 regs.
// K streamed in 256-row pipeline steps (2x128 sub-chunks): per ks the 8 Q-fragment
// LDS are amortized over BOTH sub-chunks (Q smem reads cut ~44%); 5 barriers vs 9.
#define SCHUNK 128
#define SNCH 9                      // 128-col chunks for softmax/w bookkeeping
#define SSTEP 256
#define SNST 5                      // 4 x 256 + 1 x 64
#define SCORES_SMEM ((32 * Q_STRIDE + 2 * SSTEP * KV_STRIDE + 32 * 16 + 32) * 4)

__global__ __launch_bounds__(512) void scores_kernel(
    const float* __restrict__ Qt, const float* __restrict__ Qi,
    const float* __restrict__ Kg,
    float* __restrict__ Wt, float* __restrict__ Wi)
{
    extern __shared__ float smf[];
    float* Qs      = smf;                                  // 32 x Q_STRIDE
    float* KV      = Qs + 32 * Q_STRIDE;                   // 2 x SSTEP x KV_STRIDE
    float* red     = KV + 2 * SSTEP * KV_STRIDE;           // 32 x 16
    float* rowstat = red + 32 * 16;                        // 32

    const bool isT = blockIdx.x < (ST / 32);
    const int  Sq  = isT ? ST : SI;
    const float* Q   = isT ? Qt : Qi;
    float* Wout      = isT ? Wt : Wi;
    const int qbase  = (isT ? blockIdx.x : blockIdx.x - ST / 32) * 32;

    const int z = blockIdx.y;
    const int tid  = threadIdx.x;
    const int w    = tid >> 5;          // 0..15
    const int lane = tid & 31;
    const int gid  = lane >> 2;
    const int ctid = lane & 3;

    auto issueK = [&](int s, int buf) {
        float* dst = KV + buf * SSTEP * KV_STRIDE;
        const int rows = (s == SNST - 1) ? (SKV - s * SSTEP) : SSTEP;
        for (int i = tid; i < rows * 16; i += 512) {
            const int r = i >> 4, c4 = (i & 15) * 4;
            cp16(s2u(&dst[r * KV_STRIDE + c4]), &Kg[((long long)z * SKV + s * SSTEP + r) * HDIM + c4]);
        }
        cp_commit();
    };

    // group 0: Q + K step 0
    for (int i = tid; i < 32 * 16; i += 512) {
        const int r = i >> 4, c4 = (i & 15) * 4;
        cp16(s2u(&Qs[r * Q_STRIDE + c4]), &Q[((long long)z * Sq + qbase + r) * HDIM + c4]);
    }
    issueK(0, 0);
    cp_wait0();
    __syncthreads();

    const uint32_t* Qsu = reinterpret_cast<const uint32_t*>(Qs);

    // ---- phase 1: scores into registers ----
    // thread covers rows {gid, gid+8, gid+16, gid+24}; chunk c cols {c*128 + w*8 + 2ctid, +1}
    float sacc[SNCH][2][4];
    #pragma unroll
    for (int s = 0; s < SNST; s++) {
        if (s > 0) { cp_wait0(); __syncthreads(); }
        if (s + 1 < SNST) issueK(s + 1, (s + 1) & 1);

        const uint32_t* buf = reinterpret_cast<const uint32_t*>(KV + (s & 1) * SSTEP * KV_STRIDE);
        if (s < SNST - 1) {
            // two 128-col sub-chunks; Q fragments loaded once per ks for both
            #pragma unroll
            for (int sub = 0; sub < 2; sub++)
                #pragma unroll
                for (int mf = 0; mf < 2; mf++)
                    #pragma unroll
                    for (int e = 0; e < 4; e++) sacc[s * 2 + sub][mf][e] = 0.0f;

            const int col0 = w * 8 + gid;
            #pragma unroll
            for (int ks = 0; ks < 8; ks++) {
                const int kk = ks * 8;
                uint32_t af[2][4], bf[2];
                #pragma unroll
                for (int mf = 0; mf < 2; mf++) {
                    const int r = mf * 16 + gid;
                    af[mf][0] = Qsu[r       * Q_STRIDE + kk + ctid];
                    af[mf][1] = Qsu[(r + 8) * Q_STRIDE + kk + ctid];
                    af[mf][2] = Qsu[r       * Q_STRIDE + kk + ctid + 4];
                    af[mf][3] = Qsu[(r + 8) * Q_STRIDE + kk + ctid + 4];
                }
                // sub 0
                bf[0] = buf[col0 * KV_STRIDE + kk + ctid];
                bf[1] = buf[col0 * KV_STRIDE + kk + ctid + 4];
                mma_tf32(sacc[s * 2 + 0][0], af[0], bf);
                mma_tf32(sacc[s * 2 + 0][1], af[1], bf);
                // sub 1 (cols +128)
                bf[0] = buf[(col0 + 128) * KV_STRIDE + kk + ctid];
                bf[1] = buf[(col0 + 128) * KV_STRIDE + kk + ctid + 4];
                mma_tf32(sacc[s * 2 + 1][0], af[0], bf);
                mma_tf32(sacc[s * 2 + 1][1], af[1], bf);
            }
        } else if (w < 8) {
            // tail step: 64 cols, single sub-chunk, warps 0..7 only
            #pragma unroll
            for (int mf = 0; mf < 2; mf++)
                #pragma unroll
                for (int e = 0; e < 4; e++) sacc[SNCH - 1][mf][e] = 0.0f;

            const int col0 = w * 8 + gid;
            #pragma unroll
            for (int ks = 0; ks < 8; ks++) {
                const int kk = ks * 8;
                uint32_t af[2][4], bf[2];
                #pragma unroll
                for (int mf = 0; mf < 2; mf++) {
                    const int r = mf * 16 + gid;
                    af[mf][0] = Qsu[r       * Q_STRIDE + kk + ctid];
                    af[mf][1] = Qsu[(r + 8) * Q_STRIDE + kk + ctid];
                    af[mf][2] = Qsu[r       * Q_STRIDE + kk + ctid + 4];
                    af[mf][3] = Qsu[(r + 8) * Q_STRIDE + kk + ctid + 4];
                }
                bf[0] = buf[col0 * KV_STRIDE + kk + ctid];
                bf[1] = buf[col0 * KV_STRIDE + kk + ctid + 4];
                mma_tf32(sacc[SNCH - 1][0], af[0], bf);
                mma_tf32(sacc[SNCH - 1][1], af[1], bf);
            }
        }
    }
    const bool tailAct = (w < 8);   // warps 8..15 have no chunk-8 columns

    // ---- row max ----
    float pm[4] = {-1e30f, -1e30f, -1e30f, -1e30f};
    #pragma unroll
    for (int c = 0; c < SNCH - 1; c++) {
        pm[0] = fmaxf(pm[0], fmaxf(sacc[c][0][0], sacc[c][0][1]));
        pm[1] = fmaxf(pm[1], fmaxf(sacc[c][0][2], sacc[c][0][3]));
        pm[2] = fmaxf(pm[2], fmaxf(sacc[c][1][0], sacc[c][1][1]));
        pm[3] = fmaxf(pm[3], fmaxf(sacc[c][1][2], sacc[c][1][3]));
    }
    if (tailAct) {
        pm[0] = fmaxf(pm[0], fmaxf(sacc[SNCH-1][0][0], sacc[SNCH-1][0][1]));
        pm[1] = fmaxf(pm[1], fmaxf(sacc[SNCH-1][0][2], sacc[SNCH-1][0][3]));
        pm[2] = fmaxf(pm[2], fmaxf(sacc[SNCH-1][1][0], sacc[SNCH-1][1][1]));
        pm[3] = fmaxf(pm[3], fmaxf(sacc[SNCH-1][1][2], sacc[SNCH-1][1][3]));
    }
    #pragma unroll
    for (int j = 0; j < 4; j++) {
        pm[j] = fmaxf(pm[j], __shfl_xor_sync(0xffffffffu, pm[j], 1));
        pm[j] = fmaxf(pm[j], __shfl_xor_sync(0xffffffffu, pm[j], 2));
    }
    if (ctid == 0) {
        red[gid        * 16 + w] = pm[0];
        red[(gid + 8)  * 16 + w] = pm[1];
        red[(gid + 16) * 16 + w] = pm[2];
        red[(gid + 24) * 16 + w] = pm[3];
    }
    __syncthreads();
    if (tid < 32) {
        float m = red[tid * 16];
        #pragma unroll
        for (int i = 1; i < 16; i++) m = fmaxf(m, red[tid * 16 + i]);
        rowstat[tid] = m;
    }
    __syncthreads();
    const float m0 = rowstat[gid], m1 = rowstat[gid + 8];
    const float m2 = rowstat[gid + 16], m3 = rowstat[gid + 24];

    // ---- exp in regs + row sum ----
    float ps[4] = {0.0f, 0.0f, 0.0f, 0.0f};
    #pragma unroll
    for (int c = 0; c < SNCH - 1; c++) {
        sacc[c][0][0] = __expf(sacc[c][0][0] - m0); ps[0] += sacc[c][0][0];
        sacc[c][0][1] = __expf(sacc[c][0][1] - m0); ps[0] += sacc[c][0][1];
        sacc[c][0][2] = __expf(sacc[c][0][2] - m1); ps[1] += sacc[c][0][2];
        sacc[c][0][3] = __expf(sacc[c][0][3] - m1); ps[1] += sacc[c][0][3];
        sacc[c][1][0] = __expf(sacc[c][1][0] - m2); ps[2] += sacc[c][1][0];
        sacc[c][1][1] = __expf(sacc[c][1][1] - m2); ps[2] += sacc[c][1][1];
        sacc[c][1][2] = __expf(sacc[c][1][2] - m3); ps[3] += sacc[c][1][2];
        sacc[c][1][3] = __expf(sacc[c][1][3] - m3); ps[3] += sacc[c][1][3];
    }
    if (tailAct) {
        const int c = SNCH - 1;
        sacc[c][0][0] = __expf(sacc[c][0][0] - m0); ps[0] += sacc[c][0][0];
        sacc[c][0][1] = __expf(sacc[c][0][1] - m0); ps[0] += sacc[c][0][1];
        sacc[c][0][2] = __expf(sacc[c][0][2] - m1); ps[1] += sacc[c][0][2];
        sacc[c][0][3] = __expf(sacc[c][0][3] - m1); ps[1] += sacc[c][0][3];
        sacc[c][1][0] = __expf(sacc[c][1][0] - m2); ps[2] += sacc[c][1][0];
        sacc[c][1][1] = __expf(sacc[c][1][1] - m2); ps[2] += sacc[c][1][1];
        sacc[c][1][2] = __expf(sacc[c][1][2] - m3); ps[3] += sacc[c][1][2];
        sacc[c][1][3] = __expf(sacc[c][1][3] - m3); ps[3] += sacc[c][1][3];
    }
    #pragma unroll
    for (int j = 0; j < 4; j++) {
        ps[j] += __shfl_xor_sync(0xffffffffu, ps[j], 1);
        ps[j] += __shfl_xor_sync(0xffffffffu, ps[j], 2);
    }
    __syncthreads();   // rowstat reads done before red is overwritten
    if (ctid == 0) {
        red[gid        * 16 + w] = ps[0];
        red[(gid + 8)  * 16 + w] = ps[1];
        red[(gid + 16) * 16 + w] = ps[2];
        red[(gid + 24) * 16 + w] = ps[3];
    }
    __syncthreads();
    if (tid < 32) {
        float s = red[tid * 16];
        #pragma unroll
        for (int i = 1; i < 16; i++) s += red[tid * 16 + i];
        rowstat[tid] = 1.0f / s;
    }
    __syncthreads();
    const float i0 = rowstat[gid], i1 = rowstat[gid + 8];
    const float i2 = rowstat[gid + 16], i3 = rowstat[gid + 24];

    // ---- w write from registers (streaming stores; 4x8B per 32B sector) ----
    float* base = Wout + ((long long)z * Sq + qbase) * SKV;
    #pragma unroll
    for (int c = 0; c < SNCH - 1; c++) {
        const int c0 = c * SCHUNK + w * 8 + 2 * ctid;
        stg_cs2(base + (gid)        * SKV + c0, sacc[c][0][0] * i0, sacc[c][0][1] * i0);
        stg_cs2(base + (gid + 8)  * SKV + c0, sacc[c][0][2] * i1, sacc[c][0][3] * i1);
        stg_cs2(base + (gid + 16) * SKV + c0, sacc[c][1][0] * i2, sacc[c][1][1] * i2);
        stg_cs2(base + (gid + 24) * SKV + c0, sacc[c][1][2] * i3, sacc[c][1][3] * i3);
    }
    if (tailAct) {
        const int c = SNCH - 1;
        const int c0 = c * SCHUNK + w * 8 + 2 * ctid;
        stg_cs2(base + (gid)        * SKV + c0, sacc[c][0][0] * i0, sacc[c][0][1] * i0);
        stg_cs2(base + (gid + 8)  * SKV + c0, sacc[c][0][2] * i1, sacc[c][0][3] * i1);
        stg_cs2(base + (gid + 16) * SKV + c0, sacc[c][1][0] * i2, sacc[c][1][1] * i2);
        stg_cs2(base + (gid + 24) * SKV + c0, sacc[c][1][2] * i3, sacc[c][1][3] * i3);
    }
}

// ---------------- AV kernel: O = w · V (batched 128x64x1088 tf32 GEMM) ----------------
#define AV_ASTG (128 * 36)
#define AV_BSTG (32 * KV_STRIDE)
#define AV_STG  (AV_ASTG + AV_BSTG)
#define AV_SMEM (3 * AV_STG * 4)      // 82944 bytes
#define AV_NKIT (SKV / 32)            // 34

__global__ __launch_bounds__(256, 2) void av_kernel(
    const float* __restrict__ Wt, const float* __restrict__ Wi,
    const float* __restrict__ Vg,
    float* __restrict__ Ot, float* __restrict__ Oi)
{
    extern __shared__ float smem[];
    const int mt = blockIdx.y;           // 0..3 text, 4..8 image
    const bool isT = mt < 4;
    const int Sq = isT ? ST : SI;
    const float* Wsrc = isT ? Wt : Wi;
    float* O = isT ? Ot : Oi;
    const int bm = (isT ? mt : mt - 4) * 128;
    const int z = blockIdx.z;
    const int b = z >> 4, h = z & 15;
    const float* A = Wsrc + (long long)z * Sq * SKV;
    const float* V = Vg + (long long)z * SKV * HDIM;

    const int tid  = threadIdx.x;
    const int w    = tid >> 5;
    const int lane = tid & 31;
    const int gid  = lane >> 2;
    const int ctid = lane & 3;
    const int wm = (w & 1) * 64;
    const int wn = (w >> 1) * 16;

    const int lrA = tid >> 3, lcA = (tid & 7) * 4;
    const int lrB = tid >> 4, lcB = (tid & 15) * 4;

    auto issue = [&](int k0, int s) {
        float* as = smem + s * AV_STG;
        float* bs = as + AV_ASTG;
        #pragma unroll
        for (int p = 0; p < 4; p++) {
            int ar = bm + lrA + p * 32;
            if (ar >= Sq) ar = Sq - 1;          // clamp (dup rows; stores guarded)
            cp16(s2u(&as[(lrA + p * 32) * 36 + lcA]), &A[(long long)ar * SKV + k0 + lcA]);
        }
        #pragma unroll
        for (int p = 0; p < 2; p++) {
            cp16(s2u(&bs[(lrB + p * 16) * KV_STRIDE + lcB]), &V[(long long)(k0 + lrB + p * 16) * HDIM + lcB]);
        }
        cp_commit();
    };

    float acc[4][2][4];
    #pragma unroll
    for (int i = 0; i < 4; i++)
        #pragma unroll
        for (int j = 0; j < 2; j++)
            #pragma unroll
            for (int e = 0; e < 4; e++) acc[i][j][e] = 0.0f;

    issue(0, 0);
    issue(32, 1);

    for (int it = 0; it < AV_NKIT; it++) {
        if (it == AV_NKIT - 1) cp_wait0(); else cp_wait1();
        __syncthreads();
        if (it + 2 < AV_NKIT) issue((it + 2) * 32, (it + 2) % 3);

        const float*    as = smem + (it % 3) * AV_STG;
        const uint32_t* bs = reinterpret_cast<const uint32_t*>(as + AV_ASTG);

        #pragma unroll
        for (int ks = 0; ks < 4; ks++) {
            const int kk = ks * 8;
            uint32_t af[4][4], bf[2][2];
            #pragma unroll
            for (int mf = 0; mf < 4; mf++) {
                const int r = wm + mf * 16 + gid;
                af[mf][0] = f2tf(as[r       * 36 + kk + ctid]);
                af[mf][1] = f2tf(as[(r + 8) * 36 + kk + ctid]);
                af[mf][2] = f2tf(as[r       * 36 + kk + ctid + 4]);
                af[mf][3] = f2tf(as[(r + 8) * 36 + kk + ctid + 4]);
            }
            #pragma unroll
            for (int nf = 0; nf < 2; nf++) {
                const int col = wn + nf * 8 + gid;
                bf[nf][0] = bs[(kk + ctid)     * KV_STRIDE + col];
                bf[nf][1] = bs[(kk + ctid + 4) * KV_STRIDE + col];
            }
            #pragma unroll
            for (int mf = 0; mf < 4; mf++)
                #pragma unroll
                for (int nf = 0; nf < 2; nf++)
                    mma_tf32(acc[mf][nf], af[mf], bf[nf]);
        }
    }

    #pragma unroll
    for (int mf = 0; mf < 4; mf++) {
        #pragma unroll
        for (int nf = 0; nf < 2; nf++) {
            const int r0 = bm + wm + mf * 16 + gid;
            const int c0 = h * HDIM + wn + nf * 8 + 2 * ctid;
            if (r0 < Sq) {
                float2 v = make_float2(__uint_as_float(f2tf(acc[mf][nf][0])),
                                       __uint_as_float(f2tf(acc[mf][nf][1])));
                *reinterpret_cast<float2*>(&O[((long long)b * Sq + r0) * DHID + c0]) = v;
            }
            if (r0 + 8 < Sq) {
                float2 v = make_float2(__uint_as_float(f2tf(acc[mf][nf][2])),
                                       __uint_as_float(f2tf(acc[mf][nf][3])));
                *reinterpret_cast<float2*>(&O[((long long)b * Sq + r0 + 8) * DHID + c0]) = v;
            }
        }
    }
}

// ---------------- host orchestration ----------------
extern "C" void kernel_launch(void* const* d_in, const int* in_sizes, int n_in,
                              void* d_out, int out_size)
{
    const float* q_text  = (const float*)d_in[0];
    const float* q_image = (const float*)d_in[1];
    const float* k_text  = (const float*)d_in[2];
    const float* k_image = (const float*)d_in[3];
    const float* Wq_t = (const float*)d_in[4];  const float* bq_t = (const float*)d_in[5];
    const float* Wk_t = (const float*)d_in[6];  const float* bk_t = (const float*)d_in[7];
    const float* Wv_t = (const float*)d_in[8];  const float* bv_t = (const float*)d_in[9];
    const float* Wq_i = (const float*)d_in[10]; const float* bq_i = (const float*)d_in[11];
    const float* Wk_i = (const float*)d_in[12]; const float* bk_i = (const float*)d_in[13];
    const float* Wv_i = (const float*)d_in[14]; const float* bv_i = (const float*)d_in[15];
    const float* lng_t = (const float*)d_in[16]; const float* lnb_t = (const float*)d_in[17];
    const float* lng_i = (const float*)d_in[18]; const float* lnb_i = (const float*)d_in[19];
    const float* Wo = (const float*)d_in[20]; const float* bo = (const float*)d_in[21];

    float* out = (float*)d_out;
    const long long OUT_T = 0;
    const long long OUT_I = (long long)BATCH * ST * DHID;
    const long long W_T   = OUT_I + (long long)BATCH * SI * DHID;
    const long long W_I   = W_T + (long long)BATCH * NHEAD * ST * SKV;

    float *pLNQT, *pLNQI, *pLNKT, *pLNKI, *pQT, *pQI, *pK, *pV, *pOT, *pOI, *pWc;
    cudaGetSymbolAddress((void**)&pLNQT, g_ln_qt);
    cudaGetSymbolAddress((void**)&pLNQI, g_ln_qi);
    cudaGetSymbolAddress((void**)&pLNKT, g_ln_kt);
    cudaGetSymbolAddress((void**)&pLNKI, g_ln_ki);
    cudaGetSymbolAddress((void**)&pQT,   g_Q_t);
    cudaGetSymbolAddress((void**)&pQI,   g_Q_i);
    cudaGetSymbolAddress((void**)&pK,    g_K);
    cudaGetSymbolAddress((void**)&pV,    g_V);
    cudaGetSymbolAddress((void**)&pOT,   g_O_t);
    cudaGetSymbolAddress((void**)&pOI,   g_O_i);
    cudaGetSymbolAddress((void**)&pWc,   g_Wc);

    const long long WSZ = (long long)DHID * DHID;
    float* cWq_t = pWc + 0 * WSZ;  float* cWk_t = pWc + 1 * WSZ;  float* cWv_t = pWc + 2 * WSZ;
    float* cWq_i = pWc + 3 * WSZ;  float* cWk_i = pWc + 4 * WSZ;  float* cWv_i = pWc + 5 * WSZ;
    float* cWo   = pWc + 6 * WSZ;

    cudaFuncSetAttribute(gemm_tf32_multi, cudaFuncAttributeMaxDynamicSharedMemorySize, GEMM_SMEM);
    cudaFuncSetAttribute(scores_kernel,   cudaFuncAttributeMaxDynamicSharedMemorySize, SCORES_SMEM);
    cudaFuncSetAttribute(av_kernel,       cudaFuncAttributeMaxDynamicSharedMemorySize, AV_SMEM);

    // 0) weight pre-round (7 jobs)
    {
        CvtBatch cb;
        cb.j[0] = { Wq_t, cWq_t }; cb.j[1] = { Wk_t, cWk_t }; cb.j[2] = { Wv_t, cWv_t };
        cb.j[3] = { Wq_i, cWq_i }; cb.j[4] = { Wk_i, cWk_i }; cb.j[5] = { Wv_i, cWv_i };
        cb.j[6] = { Wo, cWo };
        cvt_multi<<<dim3(DHID * DHID / (256 * 4), 7), 256>>>(cb);
    }

    // 1) LayerNorms (outputs pre-rounded tf32)
    {
        LnBatch lb;
        lb.j[0] = { q_text,  lng_t, lnb_t, pLNQT, BATCH * ST };
        lb.j[1] = { q_image, lng_i, lnb_i, pLNQI, BATCH * SI };
        lb.j[2] = { k_text,  lng_t, lnb_t, pLNKT, BATCH * ST };
        lb.j[3] = { k_image, lng_i, lnb_i, pLNKI, BATCH * SI };
        ln_multi<<<dim3(BATCH * SI, 4), 256>>>(lb);
    }

    // 2) Projections (one launch, 6 jobs)
    {
        GemmBatch gb;
        gb.j[0] = { pLNQT, cWq_t, pQT, bq_t, BATCH * ST, MODE_QSPLIT, ST, 0,  QSCALE };
        gb.j[1] = { pLNQI, cWq_i, pQI, bq_i, BATCH * SI, MODE_QSPLIT, SI, 0,  QSCALE };
        gb.j[2] = { pLNKT, cWk_t, pK,  bk_t, BATCH * ST, MODE_KV,     ST, 0,  1.0f };
        gb.j[3] = { pLNKI, cWk_i, pK,  bk_i, BATCH * SI, MODE_KV,     SI, ST, 1.0f };
        gb.j[4] = { pLNKT, cWv_t, pV,  bv_t, BATCH * ST, MODE_KV,     ST, 0,  1.0f };
        gb.j[5] = { pLNKI, cWv_i, pV,  bv_i, BATCH * SI, MODE_KV,     SI, ST, 1.0f };
        gemm_tf32_multi<<<dim3(DHID / 128, (BATCH * SI) / 128, 6), 256, GEMM_SMEM>>>(gb);
    }

    // 3) Scores + softmax + w (register-resident scores; 256-row K steps)
    scores_kernel<<<dim3(ST / 32 + SI / 32, BATCH * NHEAD), 512, SCORES_SMEM>>>(
        pQT, pQI, pK, out + W_T, out + W_I);

    // 4) O = w · V (batched GEMM, 2 CTAs/SM)
    av_kernel<<<dim3(1, 9, BATCH * NHEAD), 256, AV_SMEM>>>(
        out + W_T, out + W_I, pV, pOT, pOI);

    // 5) Output projection (one launch, 2 jobs)
    {
        GemmBatch gb;
        gb.j[0] = { pOT, cWo, out + OUT_T, bo, BATCH * ST, MODE_PLAIN, 0, 0, 1.0f };
        gb.j[1] = { pOI, cWo, out + OUT_I, bo, BATCH * SI, MODE_PLAIN, 0, 0, 1.0f };
        gb.j[2] = gb.j[1]; gb.j[3] = gb.j[1]; gb.j[4] = gb.j[1]; gb.j[5] = gb.j[1];
        gemm_tf32_multi<<<dim3(DHID / 128, (BATCH * SI) / 128, 2), 256, GEMM_SMEM>>>(gb);
    }

    (void)in_sizes; (void)n_in; (void)out_size;
}